// round 1
// baseline (speedup 1.0000x reference)
#include <cuda_runtime.h>
#include <cuda_bf16.h>

// ---------------- problem constants ----------------
#define L_SEQ   2048
#define D_MODEL 1024
#define D_INNER 2048
#define D_STATE 16
#define DT_RANK 64
#define XPROJ   96      // DT_RANK + 2*D_STATE
#define D_CONV  4

// ---------------- scratch (device globals; no allocations) ----------------
__device__ float g_xz   [L_SEQ * 2 * D_INNER];   // (2048, 4096)
__device__ float g_xconv[L_SEQ * D_INNER];       // (2048, 2048)
__device__ float g_xdbl [L_SEQ * XPROJ];         // (2048, 96)
__device__ float g_dt   [L_SEQ * D_INNER];       // (2048, 2048)
__device__ float g_u    [L_SEQ * D_INNER];       // y * silu(z)

// ---------------- generic SGEMM: C = A (MxK) * B^T (NxK) ----------------
// BM=128 BN=128 BK=8, 256 threads, 8x8 per thread.
// Requires: M%128==0, N%128==0, K%8==0, lda/ldb %4==0. (All call sites satisfy.)
// EPI: 0 = plain store, 1 = softplus(v + bias[n])
template <int EPI>
__global__ __launch_bounds__(256, 2)
void sgemm_tn(int M, int N, int K,
              const float* __restrict__ A, int lda,
              const float* __restrict__ B, int ldb,
              float* __restrict__ C, int ldc,
              const float* __restrict__ bias)
{
    const int BM = 128, BN = 128, BK = 8;
    __shared__ float As[BK][BM + 4];
    __shared__ float Bs[BK][BN + 4];

    int tid = threadIdx.x;
    int m0 = blockIdx.y * BM;
    int n0 = blockIdx.x * BN;

    int lrow  = tid >> 1;          // 0..127
    int lquad = (tid & 1) * 4;     // 0 or 4

    const float* Aptr = A + (size_t)(m0 + lrow) * lda + lquad;
    const float* Bptr = B + (size_t)(n0 + lrow) * ldb + lquad;

    int tx = tid & 15;             // 0..15
    int ty = tid >> 4;             // 0..15

    float acc[8][8];
    #pragma unroll
    for (int i = 0; i < 8; i++)
        #pragma unroll
        for (int j = 0; j < 8; j++)
            acc[i][j] = 0.f;

    for (int k0 = 0; k0 < K; k0 += BK) {
        float4 av = *(const float4*)(Aptr + k0);
        float4 bv = *(const float4*)(Bptr + k0);
        As[lquad + 0][lrow] = av.x;
        As[lquad + 1][lrow] = av.y;
        As[lquad + 2][lrow] = av.z;
        As[lquad + 3][lrow] = av.w;
        Bs[lquad + 0][lrow] = bv.x;
        Bs[lquad + 1][lrow] = bv.y;
        Bs[lquad + 2][lrow] = bv.z;
        Bs[lquad + 3][lrow] = bv.w;
        __syncthreads();

        #pragma unroll
        for (int kk = 0; kk < BK; kk++) {
            float a[8], b[8];
            #pragma unroll
            for (int i = 0; i < 8; i++) a[i] = As[kk][ty * 8 + i];
            #pragma unroll
            for (int j = 0; j < 8; j++) b[j] = Bs[kk][tx * 8 + j];
            #pragma unroll
            for (int i = 0; i < 8; i++)
                #pragma unroll
                for (int j = 0; j < 8; j++)
                    acc[i][j] = fmaf(a[i], b[j], acc[i][j]);
        }
        __syncthreads();
    }

    #pragma unroll
    for (int i = 0; i < 8; i++) {
        int row = m0 + ty * 8 + i;
        float* Crow = C + (size_t)row * ldc + n0 + tx * 8;
        #pragma unroll
        for (int j = 0; j < 8; j++) {
            float v = acc[i][j];
            if (EPI == 1) {
                v += bias[n0 + tx * 8 + j];
                // softplus
                v = (v > 20.f) ? v : log1pf(__expf(v));
            }
            Crow[j] = v;
        }
    }
}

// ---------------- depthwise causal conv (k=4) + bias + SiLU ----------------
__global__ void conv_silu_kernel(const float* __restrict__ conv_w,
                                 const float* __restrict__ conv_b)
{
    int idx = blockIdx.x * blockDim.x + threadIdx.x;
    if (idx >= L_SEQ * D_INNER) return;
    int t = idx / D_INNER;
    int d = idx % D_INNER;

    float w0 = conv_w[d * 4 + 0];
    float w1 = conv_w[d * 4 + 1];
    float w2 = conv_w[d * 4 + 2];
    float w3 = conv_w[d * 4 + 3];

    float v = conv_b[d];
    // out[t] = sum_k x[t-3+k]*w[k], x is column d of g_xz (row stride 4096)
    const float* xc = g_xz + d;
    if (t >= 3) v = fmaf(w0, xc[(size_t)(t - 3) * 4096], v);
    if (t >= 2) v = fmaf(w1, xc[(size_t)(t - 2) * 4096], v);
    if (t >= 1) v = fmaf(w2, xc[(size_t)(t - 1) * 4096], v);
    v = fmaf(w3, xc[(size_t)t * 4096], v);

    float s = 1.f / (1.f + __expf(-v));
    g_xconv[idx] = v * s;
}

// ---------------- x_dbl = x_conv (2048x2048) @ x_proj_w^T (96x2048) ----------------
// Block: 256 threads, handles 32 rows of t and all 96 outputs.
// SMEM-tiled over K in chunks of 64 so x_proj_w streams from L2 only 64x.
__global__ __launch_bounds__(256, 2)
void xproj_kernel(const float* __restrict__ x_proj_w)
{
    __shared__ float sX[32][65];
    __shared__ float sW[96][64];

    int tid = threadIdx.x;
    int t0 = blockIdx.x * 32;
    int tl = tid & 31;       // local t
    int jg = tid >> 5;       // 0..7

    float acc[12];
    #pragma unroll
    for (int i = 0; i < 12; i++) acc[i] = 0.f;

    for (int k0 = 0; k0 < D_INNER; k0 += 64) {
        // load x_conv tile 32x64
        for (int idx = tid; idx < 32 * 64; idx += 256) {
            int r = idx >> 6, c = idx & 63;
            sX[r][c] = g_xconv[(size_t)(t0 + r) * D_INNER + k0 + c];
        }
        // load weight tile 96x64
        for (int idx = tid; idx < 96 * 64; idx += 256) {
            int r = idx >> 6, c = idx & 63;
            sW[r][c] = x_proj_w[(size_t)r * D_INNER + k0 + c];
        }
        __syncthreads();

        #pragma unroll 8
        for (int k = 0; k < 64; k++) {
            float xv = sX[tl][k];
            #pragma unroll
            for (int i = 0; i < 12; i++)
                acc[i] = fmaf(xv, sW[jg + 8 * i][k], acc[i]);
        }
        __syncthreads();
    }

    #pragma unroll
    for (int i = 0; i < 12; i++)
        g_xdbl[(size_t)(t0 + tl) * XPROJ + jg + 8 * i] = acc[i];
}

// ---------------- selective scan ----------------
// thread = (d, n): d = blockIdx.x*16 + tid/16, n = tid%16
// h_{t} = exp(dt*A)*h_{t-1} + dt*x*B_t[n];  y_t[d] = sum_n h*C_t[n]
// fused: y += D[d]*x_conv; u = y * silu(z)
__global__ __launch_bounds__(256, 4)
void scan_kernel(const float* __restrict__ A_log,
                 const float* __restrict__ D_param)
{
    const int CHUNK = 128;
    __shared__ float s_BC[CHUNK][32];   // [..,0:16)=B, [..,16:32)=C
    __shared__ float s_dt[CHUNK][16];
    __shared__ float s_x [CHUNK][16];
    __shared__ float s_y [CHUNK][16];

    int tid = threadIdx.x;
    int ld  = tid >> 4;                 // local d, 0..15
    int n   = tid & 15;                 // state index
    int d0  = blockIdx.x * 16;
    int d   = d0 + ld;

    float Acoef = -__expf(A_log[(size_t)d * D_STATE + n]);
    float Dd    = D_param[d];
    float h = 0.f;

    for (int t0 = 0; t0 < L_SEQ; t0 += CHUNK) {
        // stage B,C (columns 64..95 of x_dbl)
        for (int idx = tid; idx < CHUNK * 32; idx += 256) {
            int i = idx >> 5, c = idx & 31;
            s_BC[i][c] = g_xdbl[(size_t)(t0 + i) * XPROJ + 64 + c];
        }
        // stage dt, x_conv
        for (int idx = tid; idx < CHUNK * 16; idx += 256) {
            int i = idx >> 4, dd = idx & 15;
            size_t off = (size_t)(t0 + i) * D_INNER + d0 + dd;
            s_dt[i][dd] = g_dt[off];
            s_x [i][dd] = g_xconv[off];
        }
        __syncthreads();

        for (int i = 0; i < CHUNK; i++) {
            float dtv = s_dt[i][ld];
            float xv  = s_x [i][ld];
            float dA  = __expf(dtv * Acoef);
            h = fmaf(dA, h, dtv * xv * s_BC[i][n]);
            float yc = h * s_BC[i][16 + n];
            // reduce over the 16 state lanes
            yc += __shfl_xor_sync(0xffffffffu, yc, 8, 16);
            yc += __shfl_xor_sync(0xffffffffu, yc, 4, 16);
            yc += __shfl_xor_sync(0xffffffffu, yc, 2, 16);
            yc += __shfl_xor_sync(0xffffffffu, yc, 1, 16);
            if (n == 0) s_y[i][ld] = fmaf(Dd, xv, yc);
        }
        __syncthreads();

        // coalesced store of u = y * silu(z)
        for (int idx = tid; idx < CHUNK * 16; idx += 256) {
            int i = idx >> 4, dd = idx & 15;
            int t = t0 + i, dcol = d0 + dd;
            float z = g_xz[(size_t)t * 4096 + 2048 + dcol];
            float sz = z / (1.f + __expf(-z));
            g_u[(size_t)t * D_INNER + dcol] = s_y[i][dd] * sz;
        }
        __syncthreads();
    }
}

// ---------------- launch ----------------
extern "C" void kernel_launch(void* const* d_in, const int* in_sizes, int n_in,
                              void* d_out, int out_size)
{
    const float* x         = (const float*)d_in[0];  // (1,2048,1024)
    const float* in_proj_w = (const float*)d_in[1];  // (4096,1024)
    const float* conv_w    = (const float*)d_in[2];  // (2048,1,4)
    const float* conv_b    = (const float*)d_in[3];  // (2048,)
    const float* x_proj_w  = (const float*)d_in[4];  // (96,2048)
    const float* dt_proj_w = (const float*)d_in[5];  // (2048,64)
    const float* dt_proj_b = (const float*)d_in[6];  // (2048,)
    const float* A_log     = (const float*)d_in[7];  // (2048,16)
    const float* D_param   = (const float*)d_in[8];  // (2048,)
    const float* out_proj_w= (const float*)d_in[9];  // (1024,2048)
    float* out = (float*)d_out;

    float *xz, *xconv, *xdbl, *dt, *u;
    cudaGetSymbolAddress((void**)&xz,    g_xz);
    cudaGetSymbolAddress((void**)&xconv, g_xconv);
    cudaGetSymbolAddress((void**)&xdbl,  g_xdbl);
    cudaGetSymbolAddress((void**)&dt,    g_dt);
    cudaGetSymbolAddress((void**)&u,     g_u);

    // 1) xz = x @ in_proj_w^T : (2048,4096)
    {
        dim3 grid(4096 / 128, 2048 / 128);
        sgemm_tn<0><<<grid, 256>>>(2048, 4096, 1024,
                                   x, 1024, in_proj_w, 1024, xz, 4096, nullptr);
    }
    // 2) depthwise conv + SiLU
    conv_silu_kernel<<<(L_SEQ * D_INNER + 255) / 256, 256>>>(conv_w, conv_b);
    // 3) x_dbl = x_conv @ x_proj_w^T : (2048,96)
    xproj_kernel<<<L_SEQ / 32, 256>>>(x_proj_w);
    // 4) dt = softplus(x_dbl[:, :64] @ dt_proj_w^T + b) : (2048,2048)
    {
        dim3 grid(2048 / 128, 2048 / 128);
        sgemm_tn<1><<<grid, 256>>>(2048, 2048, 64,
                                   xdbl, XPROJ, dt_proj_w, 64, dt, 2048, dt_proj_b);
    }
    // 5) selective scan (fused +D*x_conv and *silu(z))
    scan_kernel<<<D_INNER / 16, 256>>>(A_log, D_param);
    // 6) out = u @ out_proj_w^T : (2048,1024)
    {
        dim3 grid(1024 / 128, 2048 / 128);
        sgemm_tn<0><<<grid, 256>>>(2048, 1024, 2048,
                                   u, 2048, out_proj_w, 2048, out, 1024, nullptr);
    }
}

// round 3
// speedup vs baseline: 1.5115x; 1.5115x over previous
#include <cuda_runtime.h>
#include <cuda_bf16.h>
#include <cstdint>

// ---------------- problem constants ----------------
#define L_SEQ   2048
#define D_MODEL 1024
#define D_INNER 2048
#define D_STATE 16
#define DT_RANK 64
#define XPROJ   96
#define D_CONV  4

// ---------------- fp32 scratch ----------------
__device__ float g_xz   [L_SEQ * 2 * D_INNER];
__device__ float g_xconv[L_SEQ * D_INNER];
__device__ float g_xdbl [L_SEQ * XPROJ];
__device__ float g_dt   [L_SEQ * D_INNER];
__device__ float g_u    [L_SEQ * D_INNER];

// ---------------- bf16 hi/lo scratch ----------------
__device__ __nv_bfloat16 g_xh [L_SEQ * D_MODEL],      g_xl [L_SEQ * D_MODEL];
__device__ __nv_bfloat16 g_wih[2*D_INNER * D_MODEL],  g_wil[2*D_INNER * D_MODEL];
__device__ __nv_bfloat16 g_xdh[L_SEQ * XPROJ],        g_xdl[L_SEQ * XPROJ];
__device__ __nv_bfloat16 g_dwh[D_INNER * DT_RANK],    g_dwl[D_INNER * DT_RANK];
__device__ __nv_bfloat16 g_uh [L_SEQ * D_INNER],      g_ul [L_SEQ * D_INNER];
__device__ __nv_bfloat16 g_owh[D_MODEL * D_INNER],    g_owl[D_MODEL * D_INNER];

// ================= helpers =================
__device__ __forceinline__ uint32_t smem_u32(const void* p) {
    uint32_t a;
    asm("{ .reg .u64 t; cvta.to.shared.u64 t, %1; cvt.u32.u64 %0, t; }" : "=r"(a) : "l"(p));
    return a;
}
__device__ __forceinline__ void cp16(uint32_t dst, const void* src) {
    asm volatile("cp.async.cg.shared.global [%0], [%1], 16;" :: "r"(dst), "l"(src));
}
__device__ __forceinline__ void cp_commit() {
    asm volatile("cp.async.commit_group;" ::: "memory");
}
__device__ __forceinline__ void cp_wait0() {
    asm volatile("cp.async.wait_group 0;" ::: "memory");
}
__device__ __forceinline__ void ldmat4(uint32_t* r, uint32_t addr) {
    asm volatile("ldmatrix.sync.aligned.m8n8.x4.shared.b16 {%0,%1,%2,%3}, [%4];"
                 : "=r"(r[0]), "=r"(r[1]), "=r"(r[2]), "=r"(r[3]) : "r"(addr));
}
__device__ __forceinline__ void mma_bf16(float* d, const uint32_t* a, const uint32_t* b) {
    asm volatile("mma.sync.aligned.m16n8k16.row.col.f32.bf16.bf16.f32 "
                 "{%0,%1,%2,%3}, {%4,%5,%6,%7}, {%8,%9}, {%0,%1,%2,%3};"
                 : "+f"(d[0]), "+f"(d[1]), "+f"(d[2]), "+f"(d[3])
                 : "r"(a[0]), "r"(a[1]), "r"(a[2]), "r"(a[3]), "r"(b[0]), "r"(b[1]));
}

// ================= fp32 -> bf16 hi/lo split =================
__global__ void split_bf16(const float* __restrict__ in,
                           __nv_bfloat16* __restrict__ hi,
                           __nv_bfloat16* __restrict__ lo, int n)
{
    int i = blockIdx.x * blockDim.x + threadIdx.x;
    if (i >= n) return;
    float v = in[i];
    __nv_bfloat16 h = __float2bfloat16(v);
    float r = v - __bfloat162float(h);
    hi[i] = h;
    lo[i] = __float2bfloat16(r);
}

// ================= split-bf16 HMMA GEMM =================
// C(MxN) = A(MxK) @ B^T(NxK) in fp32-equivalent precision.
// CTA: 128x128, BK=32, 256 threads = 8 warps (4 m x 2 n), warp tile 32x64.
// SMEM per stage: 4 tiles (Ah, Al, Bh, Bl) of [128 rows][40 bf16] (80B pitch).
// Double buffered: 2 * 4 * 10240B = 81920B dynamic SMEM.
#define TILE_B   10240          // bytes per tile
#define STAGE_B  40960          // bytes per stage
#define DSMEM_BYTES (2 * STAGE_B)

template <int EPI>
__device__ __forceinline__ void load_stage(
    uint32_t st, const __nv_bfloat16* Ah, const __nv_bfloat16* Al, int lda,
    const __nv_bfloat16* Bh, const __nv_bfloat16* Bl, int ldb,
    int m0, int n0, int k0, int tid)
{
    #pragma unroll
    for (int j = 0; j < 2; j++) {
        int cl = tid * 2 + j;          // 0..511
        int r  = cl >> 2;              // row 0..127
        int cc = cl & 3;               // 16B chunk 0..3
        uint32_t so = (uint32_t)(r * 80 + cc * 16);
        size_t goA = (size_t)(m0 + r) * lda + k0 + cc * 8;
        size_t goB = (size_t)(n0 + r) * ldb + k0 + cc * 8;
        cp16(st + so,              Ah + goA);
        cp16(st + TILE_B + so,     Al + goA);
        cp16(st + 2 * TILE_B + so, Bh + goB);
        cp16(st + 3 * TILE_B + so, Bl + goB);
    }
    cp_commit();
}

template <int EPI>
__global__ __launch_bounds__(256)
void mma_gemm(int M, int N, int K,
              const __nv_bfloat16* __restrict__ Ah, const __nv_bfloat16* __restrict__ Al, int lda,
              const __nv_bfloat16* __restrict__ Bh, const __nv_bfloat16* __restrict__ Bl, int ldb,
              float* __restrict__ C, int ldc, const float* __restrict__ bias)
{
    extern __shared__ char smem[];
    uint32_t sbase = smem_u32(smem);

    int tid = threadIdx.x;
    int lane = tid & 31, wid = tid >> 5;
    int warp_m = wid & 3, warp_n = wid >> 2;
    int m0 = blockIdx.y * 128, n0 = blockIdx.x * 128;

    float acc[2][8][4];
    #pragma unroll
    for (int i = 0; i < 2; i++)
        #pragma unroll
        for (int j = 0; j < 8; j++)
            #pragma unroll
            for (int q = 0; q < 4; q++) acc[i][j][q] = 0.f;

    // lane-invariant smem offsets for ldmatrix
    // A: rows = warp_m*32 + mtile*16 + (lane&15); 16B chunk = kstep*2 + (lane>>4)
    uint32_t a_off = (uint32_t)((warp_m * 32 + (lane & 15)) * 80 + (lane >> 4) * 16);
    // B: rows = warp_n*64 + ntile2*16 + (lane&7) + ((lane&16)?8:0); chunk = kstep*2 + ((lane>>3)&1)
    uint32_t b_off = (uint32_t)((warp_n * 64 + ((lane & 7) | ((lane & 16) >> 1))) * 80
                                + ((lane >> 3) & 1) * 16);

    int NK = K >> 5;
    load_stage<EPI>(sbase, Ah, Al, lda, Bh, Bl, ldb, m0, n0, 0, tid);

    for (int kc = 0; kc < NK; kc++) {
        cp_wait0();
        __syncthreads();
        if (kc + 1 < NK)
            load_stage<EPI>(sbase + ((kc + 1) & 1) * STAGE_B,
                            Ah, Al, lda, Bh, Bl, ldb, m0, n0, (kc + 1) * 32, tid);

        uint32_t st = sbase + (kc & 1) * STAGE_B;
        #pragma unroll
        for (int ks = 0; ks < 2; ks++) {
            uint32_t ah[2][4], alr[2][4];
            ldmat4(ah[0],  st + a_off + ks * 32);
            ldmat4(ah[1],  st + a_off + 1280 + ks * 32);
            ldmat4(alr[0], st + TILE_B + a_off + ks * 32);
            ldmat4(alr[1], st + TILE_B + a_off + 1280 + ks * 32);

            uint32_t b[8][2];
            #pragma unroll
            for (int nj = 0; nj < 4; nj++) {
                uint32_t r4[4];
                ldmat4(r4, st + 2 * TILE_B + b_off + nj * 1280 + ks * 32);
                b[2*nj][0] = r4[0]; b[2*nj][1] = r4[1];
                b[2*nj+1][0] = r4[2]; b[2*nj+1][1] = r4[3];
            }
            #pragma unroll
            for (int mi = 0; mi < 2; mi++)
                #pragma unroll
                for (int ni = 0; ni < 8; ni++) {
                    mma_bf16(acc[mi][ni], ah[mi], b[ni]);
                    mma_bf16(acc[mi][ni], alr[mi], b[ni]);
                }
            // low half of B
            #pragma unroll
            for (int nj = 0; nj < 4; nj++) {
                uint32_t r4[4];
                ldmat4(r4, st + 3 * TILE_B + b_off + nj * 1280 + ks * 32);
                b[2*nj][0] = r4[0]; b[2*nj][1] = r4[1];
                b[2*nj+1][0] = r4[2]; b[2*nj+1][1] = r4[3];
            }
            #pragma unroll
            for (int mi = 0; mi < 2; mi++)
                #pragma unroll
                for (int ni = 0; ni < 8; ni++)
                    mma_bf16(acc[mi][ni], ah[mi], b[ni]);
        }
        __syncthreads();
    }

    // -------- epilogue --------
    int gr = lane >> 2, gc = (lane & 3) * 2;
    int row_base = m0 + warp_m * 32;
    int col_base = n0 + warp_n * 64;
    #pragma unroll
    for (int mi = 0; mi < 2; mi++) {
        #pragma unroll
        for (int ni = 0; ni < 8; ni++) {
            int r0 = row_base + mi * 16 + gr;
            int c  = col_base + ni * 8 + gc;
            float v0 = acc[mi][ni][0], v1 = acc[mi][ni][1];
            float v2 = acc[mi][ni][2], v3 = acc[mi][ni][3];
            if (EPI == 1) {
                float b0 = bias[c], b1 = bias[c + 1];
                v0 += b0; v1 += b1; v2 += b0; v3 += b1;
                v0 = (v0 > 20.f) ? v0 : log1pf(__expf(v0));
                v1 = (v1 > 20.f) ? v1 : log1pf(__expf(v1));
                v2 = (v2 > 20.f) ? v2 : log1pf(__expf(v2));
                v3 = (v3 > 20.f) ? v3 : log1pf(__expf(v3));
            }
            *(float2*)(C + (size_t)r0 * ldc + c)       = make_float2(v0, v1);
            *(float2*)(C + (size_t)(r0 + 8) * ldc + c) = make_float2(v2, v3);
        }
    }
}

// ---------------- depthwise causal conv (k=4) + bias + SiLU ----------------
__global__ void conv_silu_kernel(const float* __restrict__ conv_w,
                                 const float* __restrict__ conv_b)
{
    int idx = blockIdx.x * blockDim.x + threadIdx.x;
    if (idx >= L_SEQ * D_INNER) return;
    int t = idx / D_INNER;
    int d = idx % D_INNER;

    float w0 = conv_w[d * 4 + 0], w1 = conv_w[d * 4 + 1];
    float w2 = conv_w[d * 4 + 2], w3 = conv_w[d * 4 + 3];

    float v = conv_b[d];
    const float* xc = g_xz + d;
    if (t >= 3) v = fmaf(w0, xc[(size_t)(t - 3) * 4096], v);
    if (t >= 2) v = fmaf(w1, xc[(size_t)(t - 2) * 4096], v);
    if (t >= 1) v = fmaf(w2, xc[(size_t)(t - 1) * 4096], v);
    v = fmaf(w3, xc[(size_t)t * 4096], v);

    float s = 1.f / (1.f + __expf(-v));
    g_xconv[idx] = v * s;
}

// ---------------- x_dbl = x_conv @ x_proj_w^T (N=96) ----------------
__global__ __launch_bounds__(256, 2)
void xproj_kernel(const float* __restrict__ x_proj_w)
{
    __shared__ float sX[32][65];
    __shared__ float sW[96][64];

    int tid = threadIdx.x;
    int t0 = blockIdx.x * 32;
    int tl = tid & 31;
    int jg = tid >> 5;

    float acc[12];
    #pragma unroll
    for (int i = 0; i < 12; i++) acc[i] = 0.f;

    for (int k0 = 0; k0 < D_INNER; k0 += 64) {
        for (int idx = tid; idx < 32 * 64; idx += 256) {
            int r = idx >> 6, c = idx & 63;
            sX[r][c] = g_xconv[(size_t)(t0 + r) * D_INNER + k0 + c];
        }
        for (int idx = tid; idx < 96 * 64; idx += 256) {
            int r = idx >> 6, c = idx & 63;
            sW[r][c] = x_proj_w[(size_t)r * D_INNER + k0 + c];
        }
        __syncthreads();

        #pragma unroll 8
        for (int k = 0; k < 64; k++) {
            float xv = sX[tl][k];
            #pragma unroll
            for (int i = 0; i < 12; i++)
                acc[i] = fmaf(xv, sW[jg + 8 * i][k], acc[i]);
        }
        __syncthreads();
    }

    #pragma unroll
    for (int i = 0; i < 12; i++)
        g_xdbl[(size_t)(t0 + tl) * XPROJ + jg + 8 * i] = acc[i];
}

// ---------------- selective scan ----------------
__global__ __launch_bounds__(256, 4)
void scan_kernel(const float* __restrict__ A_log,
                 const float* __restrict__ D_param)
{
    const int CHUNK = 128;
    __shared__ float s_BC[CHUNK][32];
    __shared__ float s_dt[CHUNK][16];
    __shared__ float s_x [CHUNK][16];
    __shared__ float s_y [CHUNK][16];

    int tid = threadIdx.x;
    int ld  = tid >> 4;
    int n   = tid & 15;
    int d0  = blockIdx.x * 16;
    int d   = d0 + ld;

    float Acoef = -__expf(A_log[(size_t)d * D_STATE + n]);
    float Dd    = D_param[d];
    float h = 0.f;

    for (int t0 = 0; t0 < L_SEQ; t0 += CHUNK) {
        for (int idx = tid; idx < CHUNK * 32; idx += 256) {
            int i = idx >> 5, c = idx & 31;
            s_BC[i][c] = g_xdbl[(size_t)(t0 + i) * XPROJ + 64 + c];
        }
        for (int idx = tid; idx < CHUNK * 16; idx += 256) {
            int i = idx >> 4, dd = idx & 15;
            size_t off = (size_t)(t0 + i) * D_INNER + d0 + dd;
            s_dt[i][dd] = g_dt[off];
            s_x [i][dd] = g_xconv[off];
        }
        __syncthreads();

        for (int i = 0; i < CHUNK; i++) {
            float dtv = s_dt[i][ld];
            float xv  = s_x [i][ld];
            float dA  = __expf(dtv * Acoef);
            h = fmaf(dA, h, dtv * xv * s_BC[i][n]);
            float yc = h * s_BC[i][16 + n];
            yc += __shfl_xor_sync(0xffffffffu, yc, 8, 16);
            yc += __shfl_xor_sync(0xffffffffu, yc, 4, 16);
            yc += __shfl_xor_sync(0xffffffffu, yc, 2, 16);
            yc += __shfl_xor_sync(0xffffffffu, yc, 1, 16);
            if (n == 0) s_y[i][ld] = fmaf(Dd, xv, yc);
        }
        __syncthreads();

        for (int idx = tid; idx < CHUNK * 16; idx += 256) {
            int i = idx >> 4, dd = idx & 15;
            int t = t0 + i, dcol = d0 + dd;
            float z = g_xz[(size_t)t * 4096 + 2048 + dcol];
            float sz = z / (1.f + __expf(-z));
            g_u[(size_t)t * D_INNER + dcol] = s_y[i][dd] * sz;
        }
        __syncthreads();
    }
}

// ---------------- launch ----------------
extern "C" void kernel_launch(void* const* d_in, const int* in_sizes, int n_in,
                              void* d_out, int out_size)
{
    const float* x         = (const float*)d_in[0];
    const float* in_proj_w = (const float*)d_in[1];
    const float* conv_w    = (const float*)d_in[2];
    const float* conv_b    = (const float*)d_in[3];
    const float* x_proj_w  = (const float*)d_in[4];
    const float* dt_proj_w = (const float*)d_in[5];
    const float* dt_proj_b = (const float*)d_in[6];
    const float* A_log     = (const float*)d_in[7];
    const float* D_param   = (const float*)d_in[8];
    const float* out_proj_w= (const float*)d_in[9];
    float* out = (float*)d_out;

    float *xz, *xconv, *xdbl, *dt, *u;
    cudaGetSymbolAddress((void**)&xz,    g_xz);
    cudaGetSymbolAddress((void**)&xconv, g_xconv);
    cudaGetSymbolAddress((void**)&xdbl,  g_xdbl);
    cudaGetSymbolAddress((void**)&dt,    g_dt);
    cudaGetSymbolAddress((void**)&u,     g_u);

    __nv_bfloat16 *xh, *xl, *wih, *wil, *xdh, *xdl, *dwh, *dwl, *uh, *ul, *owh, *owl;
    cudaGetSymbolAddress((void**)&xh,  g_xh);  cudaGetSymbolAddress((void**)&xl,  g_xl);
    cudaGetSymbolAddress((void**)&wih, g_wih); cudaGetSymbolAddress((void**)&wil, g_wil);
    cudaGetSymbolAddress((void**)&xdh, g_xdh); cudaGetSymbolAddress((void**)&xdl, g_xdl);
    cudaGetSymbolAddress((void**)&dwh, g_dwh); cudaGetSymbolAddress((void**)&dwl, g_dwl);
    cudaGetSymbolAddress((void**)&uh,  g_uh);  cudaGetSymbolAddress((void**)&ul,  g_ul);
    cudaGetSymbolAddress((void**)&owh, g_owh); cudaGetSymbolAddress((void**)&owl, g_owl);

    cudaFuncSetAttribute(mma_gemm<0>, cudaFuncAttributeMaxDynamicSharedMemorySize, DSMEM_BYTES);
    cudaFuncSetAttribute(mma_gemm<1>, cudaFuncAttributeMaxDynamicSharedMemorySize, DSMEM_BYTES);

    const int ST = 256;
    // --- GEMM1 inputs ---
    split_bf16<<<(L_SEQ * D_MODEL + ST - 1) / ST, ST>>>(x, xh, xl, L_SEQ * D_MODEL);
    split_bf16<<<(2 * D_INNER * D_MODEL + ST - 1) / ST, ST>>>(in_proj_w, wih, wil, 2 * D_INNER * D_MODEL);

    // 1) xz = x @ in_proj_w^T : (2048, 4096)
    {
        dim3 grid(4096 / 128, 2048 / 128);
        mma_gemm<0><<<grid, 256, DSMEM_BYTES>>>(2048, 4096, 1024,
            xh, xl, 1024, wih, wil, 1024, xz, 4096, nullptr);
    }
    // 2) conv + SiLU
    conv_silu_kernel<<<(L_SEQ * D_INNER + ST - 1) / ST, ST>>>(conv_w, conv_b);
    // 3) x_dbl
    xproj_kernel<<<L_SEQ / 32, 256>>>(x_proj_w);
    // 4) dt = softplus(x_dbl[:, :64] @ dt_proj_w^T + b)
    split_bf16<<<(L_SEQ * XPROJ + ST - 1) / ST, ST>>>(xdbl, xdh, xdl, L_SEQ * XPROJ);
    split_bf16<<<(D_INNER * DT_RANK + ST - 1) / ST, ST>>>(dt_proj_w, dwh, dwl, D_INNER * DT_RANK);
    {
        dim3 grid(2048 / 128, 2048 / 128);
        mma_gemm<1><<<grid, 256, DSMEM_BYTES>>>(2048, 2048, 64,
            xdh, xdl, XPROJ, dwh, dwl, DT_RANK, dt, 2048, dt_proj_b);
    }
    // 5) scan
    scan_kernel<<<D_INNER / 16, 256>>>(A_log, D_param);
    // 6) out = u @ out_proj_w^T
    split_bf16<<<(L_SEQ * D_INNER + ST - 1) / ST, ST>>>(u, uh, ul, L_SEQ * D_INNER);
    split_bf16<<<(D_MODEL * D_INNER + ST - 1) / ST, ST>>>(out_proj_w, owh, owl, D_MODEL * D_INNER);
    {
        dim3 grid(1024 / 128, 2048 / 128);
        mma_gemm<0><<<grid, 256, DSMEM_BYTES>>>(2048, 1024, 2048,
            uh, ul, 2048, owh, owl, 2048, out, 1024, nullptr);
    }
}

// round 4
// speedup vs baseline: 1.5767x; 1.0431x over previous
#include <cuda_runtime.h>
#include <cuda_bf16.h>
#include <cstdint>

// ---------------- problem constants ----------------
#define L_SEQ   2048
#define D_MODEL 1024
#define D_INNER 2048
#define D_STATE 16
#define DT_RANK 64
#define XPROJ   96
#define D_CONV  4

// ---------------- fp32 scratch ----------------
__device__ float g_xz   [L_SEQ * 2 * D_INNER];
__device__ float g_xconv[L_SEQ * D_INNER];
__device__ float g_xdbl [L_SEQ * XPROJ];
__device__ float g_dt   [L_SEQ * D_INNER];

// ---------------- bf16 hi/lo scratch ----------------
__device__ __nv_bfloat16 g_xh [L_SEQ * D_MODEL],      g_xl [L_SEQ * D_MODEL];
__device__ __nv_bfloat16 g_wih[2*D_INNER * D_MODEL],  g_wil[2*D_INNER * D_MODEL];
__device__ __nv_bfloat16 g_xdh[L_SEQ * XPROJ],        g_xdl[L_SEQ * XPROJ];
__device__ __nv_bfloat16 g_dwh[D_INNER * DT_RANK],    g_dwl[D_INNER * DT_RANK];
__device__ __nv_bfloat16 g_uh [L_SEQ * D_INNER],      g_ul [L_SEQ * D_INNER];
__device__ __nv_bfloat16 g_owh[D_MODEL * D_INNER],    g_owl[D_MODEL * D_INNER];

// ================= helpers =================
__device__ __forceinline__ uint32_t smem_u32(const void* p) {
    uint32_t a;
    asm("{ .reg .u64 t; cvta.to.shared.u64 t, %1; cvt.u32.u64 %0, t; }" : "=r"(a) : "l"(p));
    return a;
}
__device__ __forceinline__ void cp16(uint32_t dst, const void* src) {
    asm volatile("cp.async.cg.shared.global [%0], [%1], 16;" :: "r"(dst), "l"(src));
}
__device__ __forceinline__ void cp_commit() {
    asm volatile("cp.async.commit_group;" ::: "memory");
}
__device__ __forceinline__ void cp_wait0() {
    asm volatile("cp.async.wait_group 0;" ::: "memory");
}
__device__ __forceinline__ void ldmat4(uint32_t* r, uint32_t addr) {
    asm volatile("ldmatrix.sync.aligned.m8n8.x4.shared.b16 {%0,%1,%2,%3}, [%4];"
                 : "=r"(r[0]), "=r"(r[1]), "=r"(r[2]), "=r"(r[3]) : "r"(addr));
}
__device__ __forceinline__ void mma_bf16(float* d, const uint32_t* a, const uint32_t* b) {
    asm volatile("mma.sync.aligned.m16n8k16.row.col.f32.bf16.bf16.f32 "
                 "{%0,%1,%2,%3}, {%4,%5,%6,%7}, {%8,%9}, {%0,%1,%2,%3};"
                 : "+f"(d[0]), "+f"(d[1]), "+f"(d[2]), "+f"(d[3])
                 : "r"(a[0]), "r"(a[1]), "r"(a[2]), "r"(a[3]), "r"(b[0]), "r"(b[1]));
}
__device__ __forceinline__ void split1(float v, __nv_bfloat16& h, __nv_bfloat16& l) {
    h = __float2bfloat16(v);
    l = __float2bfloat16(v - __bfloat162float(h));
}

// ================= fp32 -> bf16 hi/lo split =================
__global__ void split_bf16(const float* __restrict__ in,
                           __nv_bfloat16* __restrict__ hi,
                           __nv_bfloat16* __restrict__ lo, int n)
{
    int i = blockIdx.x * blockDim.x + threadIdx.x;
    if (i >= n) return;
    float v = in[i];
    __nv_bfloat16 h, l;
    split1(v, h, l);
    hi[i] = h;
    lo[i] = l;
}

// ================= split-bf16 HMMA GEMM =================
// C(MxN) = A(MxK) @ B^T(NxK), fp32-equivalent via Ah*Bh + Al*Bh + Ah*Bl.
// CTA: 128x128, BK=32, 256 threads = 8 warps (4 m x 2 n), warp tile 32x64.
// SMEM per stage: 4 tiles of [128][40] bf16 (80B pitch). Double buffered.
#define TILE_B   10240
#define STAGE_B  40960
#define DSMEM_BYTES (2 * STAGE_B)

__device__ __forceinline__ void load_stage(
    uint32_t st, const __nv_bfloat16* Ah, const __nv_bfloat16* Al, int lda,
    const __nv_bfloat16* Bh, const __nv_bfloat16* Bl, int ldb,
    int m0, int n0, int k0, int tid)
{
    #pragma unroll
    for (int j = 0; j < 2; j++) {
        int cl = tid * 2 + j;
        int r  = cl >> 2;
        int cc = cl & 3;
        uint32_t so = (uint32_t)(r * 80 + cc * 16);
        size_t goA = (size_t)(m0 + r) * lda + k0 + cc * 8;
        size_t goB = (size_t)(n0 + r) * ldb + k0 + cc * 8;
        cp16(st + so,              Ah + goA);
        cp16(st + TILE_B + so,     Al + goA);
        cp16(st + 2 * TILE_B + so, Bh + goB);
        cp16(st + 3 * TILE_B + so, Bl + goB);
    }
    cp_commit();
}

template <int EPI>
__global__ __launch_bounds__(256, 2)
void mma_gemm(int M, int N, int K,
              const __nv_bfloat16* __restrict__ Ah, const __nv_bfloat16* __restrict__ Al, int lda,
              const __nv_bfloat16* __restrict__ Bh, const __nv_bfloat16* __restrict__ Bl, int ldb,
              float* __restrict__ C, int ldc, const float* __restrict__ bias)
{
    extern __shared__ char smem[];
    uint32_t sbase = smem_u32(smem);

    int tid = threadIdx.x;
    int lane = tid & 31, wid = tid >> 5;
    int warp_m = wid & 3, warp_n = wid >> 2;
    int m0 = blockIdx.y * 128, n0 = blockIdx.x * 128;

    float acc[2][8][4];
    #pragma unroll
    for (int i = 0; i < 2; i++)
        #pragma unroll
        for (int j = 0; j < 8; j++)
            #pragma unroll
            for (int q = 0; q < 4; q++) acc[i][j][q] = 0.f;

    uint32_t a_off = (uint32_t)((warp_m * 32 + (lane & 15)) * 80 + (lane >> 4) * 16);
    uint32_t b_off = (uint32_t)((warp_n * 64 + ((lane & 7) | ((lane & 16) >> 1))) * 80
                                + ((lane >> 3) & 1) * 16);

    int NK = K >> 5;
    load_stage(sbase, Ah, Al, lda, Bh, Bl, ldb, m0, n0, 0, tid);

    for (int kc = 0; kc < NK; kc++) {
        cp_wait0();
        __syncthreads();
        if (kc + 1 < NK)
            load_stage(sbase + ((kc + 1) & 1) * STAGE_B,
                       Ah, Al, lda, Bh, Bl, ldb, m0, n0, (kc + 1) * 32, tid);

        uint32_t st = sbase + (kc & 1) * STAGE_B;
        #pragma unroll
        for (int ks = 0; ks < 2; ks++) {
            uint32_t ah[2][4], al[2][4], b[8][2];
            ldmat4(ah[0], st + a_off + ks * 32);
            ldmat4(ah[1], st + a_off + 1280 + ks * 32);
            ldmat4(al[0], st + TILE_B + a_off + ks * 32);
            ldmat4(al[1], st + TILE_B + a_off + 1280 + ks * 32);

            // B-hi
            #pragma unroll
            for (int nj = 0; nj < 4; nj++) {
                uint32_t r4[4];
                ldmat4(r4, st + 2 * TILE_B + b_off + nj * 1280 + ks * 32);
                b[2*nj][0] = r4[0]; b[2*nj][1] = r4[1];
                b[2*nj+1][0] = r4[2]; b[2*nj+1][1] = r4[3];
            }
            // pass 1: Ah * Bh  (16 distinct accumulators back-to-back)
            #pragma unroll
            for (int mi = 0; mi < 2; mi++)
                #pragma unroll
                for (int ni = 0; ni < 8; ni++)
                    mma_bf16(acc[mi][ni], ah[mi], b[ni]);
            // pass 2: Al * Bh
            #pragma unroll
            for (int mi = 0; mi < 2; mi++)
                #pragma unroll
                for (int ni = 0; ni < 8; ni++)
                    mma_bf16(acc[mi][ni], al[mi], b[ni]);
            // B-lo (reuse b regs)
            #pragma unroll
            for (int nj = 0; nj < 4; nj++) {
                uint32_t r4[4];
                ldmat4(r4, st + 3 * TILE_B + b_off + nj * 1280 + ks * 32);
                b[2*nj][0] = r4[0]; b[2*nj][1] = r4[1];
                b[2*nj+1][0] = r4[2]; b[2*nj+1][1] = r4[3];
            }
            // pass 3: Ah * Bl
            #pragma unroll
            for (int mi = 0; mi < 2; mi++)
                #pragma unroll
                for (int ni = 0; ni < 8; ni++)
                    mma_bf16(acc[mi][ni], ah[mi], b[ni]);
        }
        __syncthreads();
    }

    // -------- epilogue --------
    int gr = lane >> 2, gc = (lane & 3) * 2;
    int row_base = m0 + warp_m * 32;
    int col_base = n0 + warp_n * 64;
    #pragma unroll
    for (int mi = 0; mi < 2; mi++) {
        #pragma unroll
        for (int ni = 0; ni < 8; ni++) {
            int r0 = row_base + mi * 16 + gr;
            int c  = col_base + ni * 8 + gc;
            float v0 = acc[mi][ni][0], v1 = acc[mi][ni][1];
            float v2 = acc[mi][ni][2], v3 = acc[mi][ni][3];
            if (EPI == 1) {
                float b0 = bias[c], b1 = bias[c + 1];
                v0 += b0; v1 += b1; v2 += b0; v3 += b1;
                v0 = (v0 > 20.f) ? v0 : log1pf(__expf(v0));
                v1 = (v1 > 20.f) ? v1 : log1pf(__expf(v1));
                v2 = (v2 > 20.f) ? v2 : log1pf(__expf(v2));
                v3 = (v3 > 20.f) ? v3 : log1pf(__expf(v3));
            }
            *(float2*)(C + (size_t)r0 * ldc + c)       = make_float2(v0, v1);
            *(float2*)(C + (size_t)(r0 + 8) * ldc + c) = make_float2(v2, v3);
        }
    }
}

// ---------------- depthwise causal conv (k=4) + bias + SiLU ----------------
__global__ void conv_silu_kernel(const float* __restrict__ conv_w,
                                 const float* __restrict__ conv_b)
{
    int idx = blockIdx.x * blockDim.x + threadIdx.x;
    if (idx >= L_SEQ * D_INNER) return;
    int t = idx / D_INNER;
    int d = idx % D_INNER;

    float w0 = conv_w[d * 4 + 0], w1 = conv_w[d * 4 + 1];
    float w2 = conv_w[d * 4 + 2], w3 = conv_w[d * 4 + 3];

    float v = conv_b[d];
    const float* xc = g_xz + d;
    if (t >= 3) v = fmaf(w0, xc[(size_t)(t - 3) * 4096], v);
    if (t >= 2) v = fmaf(w1, xc[(size_t)(t - 2) * 4096], v);
    if (t >= 1) v = fmaf(w2, xc[(size_t)(t - 1) * 4096], v);
    v = fmaf(w3, xc[(size_t)t * 4096], v);

    float s = 1.f / (1.f + __expf(-v));
    g_xconv[idx] = v * s;
}

// ---------------- x_dbl = x_conv @ x_proj_w^T (N=96), emits fp32 + hi/lo ----------------
__global__ __launch_bounds__(256, 2)
void xproj_kernel(const float* __restrict__ x_proj_w)
{
    __shared__ float sX[32][65];
    __shared__ float sW[96][64];

    int tid = threadIdx.x;
    int t0 = blockIdx.x * 32;
    int tl = tid & 31;
    int jg = tid >> 5;

    float acc[12];
    #pragma unroll
    for (int i = 0; i < 12; i++) acc[i] = 0.f;

    for (int k0 = 0; k0 < D_INNER; k0 += 64) {
        for (int idx = tid; idx < 32 * 64; idx += 256) {
            int r = idx >> 6, c = idx & 63;
            sX[r][c] = g_xconv[(size_t)(t0 + r) * D_INNER + k0 + c];
        }
        for (int idx = tid; idx < 96 * 64; idx += 256) {
            int r = idx >> 6, c = idx & 63;
            sW[r][c] = x_proj_w[(size_t)r * D_INNER + k0 + c];
        }
        __syncthreads();

        #pragma unroll 8
        for (int k = 0; k < 64; k++) {
            float xv = sX[tl][k];
            #pragma unroll
            for (int i = 0; i < 12; i++)
                acc[i] = fmaf(xv, sW[jg + 8 * i][k], acc[i]);
        }
        __syncthreads();
    }

    #pragma unroll
    for (int i = 0; i < 12; i++) {
        size_t o = (size_t)(t0 + tl) * XPROJ + jg + 8 * i;
        float v = acc[i];
        g_xdbl[o] = v;
        __nv_bfloat16 h, l;
        split1(v, h, l);
        g_xdh[o] = h;
        g_xdl[o] = l;
    }
}

// ---------------- selective scan (emits u as bf16 hi/lo) ----------------
__global__ __launch_bounds__(256, 4)
void scan_kernel(const float* __restrict__ A_log,
                 const float* __restrict__ D_param)
{
    const int CHUNK = 128;
    __shared__ float s_BC[CHUNK][32];
    __shared__ float s_dt[CHUNK][16];
    __shared__ float s_x [CHUNK][16];
    __shared__ float s_y [CHUNK][16];

    int tid = threadIdx.x;
    int ld  = tid >> 4;
    int n   = tid & 15;
    int d0  = blockIdx.x * 16;
    int d   = d0 + ld;

    float Acoef = -__expf(A_log[(size_t)d * D_STATE + n]);
    float Dd    = D_param[d];
    float h = 0.f;

    for (int t0 = 0; t0 < L_SEQ; t0 += CHUNK) {
        for (int idx = tid; idx < CHUNK * 32; idx += 256) {
            int i = idx >> 5, c = idx & 31;
            s_BC[i][c] = g_xdbl[(size_t)(t0 + i) * XPROJ + 64 + c];
        }
        for (int idx = tid; idx < CHUNK * 16; idx += 256) {
            int i = idx >> 4, dd = idx & 15;
            size_t off = (size_t)(t0 + i) * D_INNER + d0 + dd;
            s_dt[i][dd] = g_dt[off];
            s_x [i][dd] = g_xconv[off];
        }
        __syncthreads();

        for (int i = 0; i < CHUNK; i++) {
            float dtv = s_dt[i][ld];
            float xv  = s_x [i][ld];
            float dA  = __expf(dtv * Acoef);
            h = fmaf(dA, h, dtv * xv * s_BC[i][n]);
            float yc = h * s_BC[i][16 + n];
            yc += __shfl_xor_sync(0xffffffffu, yc, 8, 16);
            yc += __shfl_xor_sync(0xffffffffu, yc, 4, 16);
            yc += __shfl_xor_sync(0xffffffffu, yc, 2, 16);
            yc += __shfl_xor_sync(0xffffffffu, yc, 1, 16);
            if (n == 0) s_y[i][ld] = fmaf(Dd, xv, yc);
        }
        __syncthreads();

        for (int idx = tid; idx < CHUNK * 16; idx += 256) {
            int i = idx >> 4, dd = idx & 15;
            int t = t0 + i, dcol = d0 + dd;
            float z = g_xz[(size_t)t * 4096 + 2048 + dcol];
            float sz = z / (1.f + __expf(-z));
            float u = s_y[i][dd] * sz;
            __nv_bfloat16 uh, ul;
            split1(u, uh, ul);
            size_t o = (size_t)t * D_INNER + dcol;
            g_uh[o] = uh;
            g_ul[o] = ul;
        }
        __syncthreads();
    }
}

// ---------------- launch ----------------
extern "C" void kernel_launch(void* const* d_in, const int* in_sizes, int n_in,
                              void* d_out, int out_size)
{
    const float* x         = (const float*)d_in[0];
    const float* in_proj_w = (const float*)d_in[1];
    const float* conv_w    = (const float*)d_in[2];
    const float* conv_b    = (const float*)d_in[3];
    const float* x_proj_w  = (const float*)d_in[4];
    const float* dt_proj_w = (const float*)d_in[5];
    const float* dt_proj_b = (const float*)d_in[6];
    const float* A_log     = (const float*)d_in[7];
    const float* D_param   = (const float*)d_in[8];
    const float* out_proj_w= (const float*)d_in[9];
    float* out = (float*)d_out;

    float *xz, *dt;
    cudaGetSymbolAddress((void**)&xz, g_xz);
    cudaGetSymbolAddress((void**)&dt, g_dt);

    __nv_bfloat16 *xh, *xl, *wih, *wil, *xdh, *xdl, *dwh, *dwl, *uh, *ul, *owh, *owl;
    cudaGetSymbolAddress((void**)&xh,  g_xh);  cudaGetSymbolAddress((void**)&xl,  g_xl);
    cudaGetSymbolAddress((void**)&wih, g_wih); cudaGetSymbolAddress((void**)&wil, g_wil);
    cudaGetSymbolAddress((void**)&xdh, g_xdh); cudaGetSymbolAddress((void**)&xdl, g_xdl);
    cudaGetSymbolAddress((void**)&dwh, g_dwh); cudaGetSymbolAddress((void**)&dwl, g_dwl);
    cudaGetSymbolAddress((void**)&uh,  g_uh);  cudaGetSymbolAddress((void**)&ul,  g_ul);
    cudaGetSymbolAddress((void**)&owh, g_owh); cudaGetSymbolAddress((void**)&owl, g_owl);

    cudaFuncSetAttribute(mma_gemm<0>, cudaFuncAttributeMaxDynamicSharedMemorySize, DSMEM_BYTES);
    cudaFuncSetAttribute(mma_gemm<1>, cudaFuncAttributeMaxDynamicSharedMemorySize, DSMEM_BYTES);

    const int ST = 256;
    split_bf16<<<(L_SEQ * D_MODEL + ST - 1) / ST, ST>>>(x, xh, xl, L_SEQ * D_MODEL);
    split_bf16<<<(2 * D_INNER * D_MODEL + ST - 1) / ST, ST>>>(in_proj_w, wih, wil, 2 * D_INNER * D_MODEL);

    // 1) xz = x @ in_proj_w^T : (2048, 4096)
    {
        dim3 grid(4096 / 128, 2048 / 128);
        mma_gemm<0><<<grid, 256, DSMEM_BYTES>>>(2048, 4096, 1024,
            xh, xl, 1024, wih, wil, 1024, xz, 4096, nullptr);
    }
    // 2) conv + SiLU
    conv_silu_kernel<<<(L_SEQ * D_INNER + ST - 1) / ST, ST>>>(conv_w, conv_b);
    // 3) x_dbl (+ inline hi/lo split)
    xproj_kernel<<<L_SEQ / 32, 256>>>(x_proj_w);
    // 4) dt = softplus(x_dbl[:, :64] @ dt_proj_w^T + b)
    split_bf16<<<(D_INNER * DT_RANK + ST - 1) / ST, ST>>>(dt_proj_w, dwh, dwl, D_INNER * DT_RANK);
    {
        dim3 grid(2048 / 128, 2048 / 128);
        mma_gemm<1><<<grid, 256, DSMEM_BYTES>>>(2048, 2048, 64,
            xdh, xdl, XPROJ, dwh, dwl, DT_RANK, dt, 2048, dt_proj_b);
    }
    // 5) scan (+ inline u hi/lo split)
    scan_kernel<<<D_INNER / 16, 256>>>(A_log, D_param);
    // 6) out = u @ out_proj_w^T
    split_bf16<<<(D_MODEL * D_INNER + ST - 1) / ST, ST>>>(out_proj_w, owh, owl, D_MODEL * D_INNER);
    {
        dim3 grid(1024 / 128, 2048 / 128);
        mma_gemm<0><<<grid, 256, DSMEM_BYTES>>>(2048, 1024, 2048,
            uh, ul, 2048, owh, owl, 2048, out, 1024, nullptr);
    }
}

// round 5
// speedup vs baseline: 1.7608x; 1.1168x over previous
#include <cuda_runtime.h>
#include <cuda_fp16.h>
#include <cstdint>

// ---------------- problem constants ----------------
#define L_SEQ   2048
#define D_MODEL 1024
#define D_INNER 2048
#define D_STATE 16
#define DT_RANK 64
#define XPROJ   96
#define D_CONV  4

// ---------------- fp32 scratch ----------------
__device__ float g_xz   [L_SEQ * 2 * D_INNER];
__device__ float g_xconv[L_SEQ * D_INNER];
__device__ float g_xdbl [L_SEQ * XPROJ];
__device__ float g_dt   [L_SEQ * D_INNER];

// ---------------- fp16 hi/lo scratch ----------------
__device__ __half g_xh [L_SEQ * D_MODEL],      g_xl [L_SEQ * D_MODEL];
__device__ __half g_wih[2*D_INNER * D_MODEL];   // weights hi only (B operand)
__device__ __half g_xdh[L_SEQ * XPROJ],        g_xdl[L_SEQ * XPROJ];
__device__ __half g_dwh[D_INNER * DT_RANK];
__device__ __half g_uh [L_SEQ * D_INNER],      g_ul [L_SEQ * D_INNER];
__device__ __half g_owh[D_MODEL * D_INNER];

// ================= helpers =================
__device__ __forceinline__ uint32_t smem_u32(const void* p) {
    uint32_t a;
    asm("{ .reg .u64 t; cvta.to.shared.u64 t, %1; cvt.u32.u64 %0, t; }" : "=r"(a) : "l"(p));
    return a;
}
__device__ __forceinline__ void cp16(uint32_t dst, const void* src) {
    asm volatile("cp.async.cg.shared.global [%0], [%1], 16;" :: "r"(dst), "l"(src));
}
__device__ __forceinline__ void cp_commit() {
    asm volatile("cp.async.commit_group;" ::: "memory");
}
__device__ __forceinline__ void cp_wait0() {
    asm volatile("cp.async.wait_group 0;" ::: "memory");
}
__device__ __forceinline__ void ldmat4(uint32_t* r, uint32_t addr) {
    asm volatile("ldmatrix.sync.aligned.m8n8.x4.shared.b16 {%0,%1,%2,%3}, [%4];"
                 : "=r"(r[0]), "=r"(r[1]), "=r"(r[2]), "=r"(r[3]) : "r"(addr));
}
__device__ __forceinline__ void mma_f16(float* d, const uint32_t* a, const uint32_t* b) {
    asm volatile("mma.sync.aligned.m16n8k16.row.col.f32.f16.f16.f32 "
                 "{%0,%1,%2,%3}, {%4,%5,%6,%7}, {%8,%9}, {%0,%1,%2,%3};"
                 : "+f"(d[0]), "+f"(d[1]), "+f"(d[2]), "+f"(d[3])
                 : "r"(a[0]), "r"(a[1]), "r"(a[2]), "r"(a[3]), "r"(b[0]), "r"(b[1]));
}
__device__ __forceinline__ void split1(float v, __half& h, __half& l) {
    h = __float2half_rn(v);
    l = __float2half_rn(v - __half2float(h));
}

// ================= fp32 -> fp16 hi/lo split =================
__global__ void split_f16(const float* __restrict__ in,
                          __half* __restrict__ hi,
                          __half* __restrict__ lo, int n)
{
    int i = blockIdx.x * blockDim.x + threadIdx.x;
    if (i >= n) return;
    float v = in[i];
    __half h, l;
    split1(v, h, l);
    hi[i] = h;
    if (lo) lo[i] = l;
}

// ================= split-fp16 HMMA GEMM =================
// C(MxN) = A(MxK) @ B^T(NxK); A = Ah + Al (fp16 pair), B = Bh (fp16).
// Error ~ 2^-12 relative (A*Bl term dropped). 2 MMA passes per tile.
// CTA: 128x128, BK=32, 256 threads = 8 warps (4m x 2n), warp tile 32x64.
// SMEM/stage: 3 tiles of [128][40] fp16 (80B pitch) = 30720B; double buffered.
#define TILE_B   10240
#define STAGE_B  30720
#define DSMEM_BYTES (2 * STAGE_B)

__device__ __forceinline__ void load_stage(
    uint32_t st, const __half* Ah, const __half* Al, int lda,
    const __half* Bh, int ldb, int m0, int n0, int k0, int tid)
{
    #pragma unroll
    for (int j = 0; j < 2; j++) {
        int cl = tid * 2 + j;
        int r  = cl >> 2;
        int cc = cl & 3;
        uint32_t so = (uint32_t)(r * 80 + cc * 16);
        size_t goA = (size_t)(m0 + r) * lda + k0 + cc * 8;
        size_t goB = (size_t)(n0 + r) * ldb + k0 + cc * 8;
        cp16(st + so,              Ah + goA);
        cp16(st + TILE_B + so,     Al + goA);
        cp16(st + 2 * TILE_B + so, Bh + goB);
    }
    cp_commit();
}

template <int EPI>
__global__ __launch_bounds__(256, 2)
void mma_gemm(int M, int N, int K,
              const __half* __restrict__ Ah, const __half* __restrict__ Al, int lda,
              const __half* __restrict__ Bh, int ldb,
              float* __restrict__ C, int ldc, const float* __restrict__ bias)
{
    extern __shared__ char smem[];
    uint32_t sbase = smem_u32(smem);

    int tid = threadIdx.x;
    int lane = tid & 31, wid = tid >> 5;
    int warp_m = wid & 3, warp_n = wid >> 2;
    int m0 = blockIdx.y * 128, n0 = blockIdx.x * 128;

    float acc[2][8][4];
    #pragma unroll
    for (int i = 0; i < 2; i++)
        #pragma unroll
        for (int j = 0; j < 8; j++)
            #pragma unroll
            for (int q = 0; q < 4; q++) acc[i][j][q] = 0.f;

    uint32_t a_off = (uint32_t)((warp_m * 32 + (lane & 15)) * 80 + (lane >> 4) * 16);
    uint32_t b_off = (uint32_t)((warp_n * 64 + ((lane & 7) | ((lane & 16) >> 1))) * 80
                                + ((lane >> 3) & 1) * 16);

    int NK = K >> 5;
    load_stage(sbase, Ah, Al, lda, Bh, ldb, m0, n0, 0, tid);

    for (int kc = 0; kc < NK; kc++) {
        cp_wait0();
        __syncthreads();
        if (kc + 1 < NK)
            load_stage(sbase + ((kc + 1) & 1) * STAGE_B,
                       Ah, Al, lda, Bh, ldb, m0, n0, (kc + 1) * 32, tid);

        uint32_t st = sbase + (kc & 1) * STAGE_B;
        #pragma unroll
        for (int ks = 0; ks < 2; ks++) {
            uint32_t ah[2][4], al[2][4];
            ldmat4(ah[0], st + a_off + ks * 32);
            ldmat4(ah[1], st + a_off + 1280 + ks * 32);
            ldmat4(al[0], st + TILE_B + a_off + ks * 32);
            ldmat4(al[1], st + TILE_B + a_off + 1280 + ks * 32);

            #pragma unroll
            for (int half = 0; half < 2; half++) {
                uint32_t b[4][2];
                #pragma unroll
                for (int nj = 0; nj < 2; nj++) {
                    uint32_t r4[4];
                    ldmat4(r4, st + 2 * TILE_B + b_off + (half * 2 + nj) * 1280 + ks * 32);
                    b[2*nj][0] = r4[0]; b[2*nj][1] = r4[1];
                    b[2*nj+1][0] = r4[2]; b[2*nj+1][1] = r4[3];
                }
                // pass 1: Ah * Bh  (8 distinct accumulators)
                #pragma unroll
                for (int mi = 0; mi < 2; mi++)
                    #pragma unroll
                    for (int ni = 0; ni < 4; ni++)
                        mma_f16(acc[mi][half * 4 + ni], ah[mi], b[ni]);
                // pass 2: Al * Bh
                #pragma unroll
                for (int mi = 0; mi < 2; mi++)
                    #pragma unroll
                    for (int ni = 0; ni < 4; ni++)
                        mma_f16(acc[mi][half * 4 + ni], al[mi], b[ni]);
            }
        }
        __syncthreads();
    }

    // -------- epilogue --------
    int gr = lane >> 2, gc = (lane & 3) * 2;
    int row_base = m0 + warp_m * 32;
    int col_base = n0 + warp_n * 64;
    #pragma unroll
    for (int mi = 0; mi < 2; mi++) {
        #pragma unroll
        for (int ni = 0; ni < 8; ni++) {
            int r0 = row_base + mi * 16 + gr;
            int c  = col_base + ni * 8 + gc;
            float v0 = acc[mi][ni][0], v1 = acc[mi][ni][1];
            float v2 = acc[mi][ni][2], v3 = acc[mi][ni][3];
            if (EPI == 1) {
                float b0 = bias[c], b1 = bias[c + 1];
                v0 += b0; v1 += b1; v2 += b0; v3 += b1;
                v0 = (v0 > 20.f) ? v0 : log1pf(__expf(v0));
                v1 = (v1 > 20.f) ? v1 : log1pf(__expf(v1));
                v2 = (v2 > 20.f) ? v2 : log1pf(__expf(v2));
                v3 = (v3 > 20.f) ? v3 : log1pf(__expf(v3));
            }
            *(float2*)(C + (size_t)r0 * ldc + c)       = make_float2(v0, v1);
            *(float2*)(C + (size_t)(r0 + 8) * ldc + c) = make_float2(v2, v3);
        }
    }
}

// ---------------- depthwise causal conv (k=4) + bias + SiLU ----------------
__global__ void conv_silu_kernel(const float* __restrict__ conv_w,
                                 const float* __restrict__ conv_b)
{
    int idx = blockIdx.x * blockDim.x + threadIdx.x;
    if (idx >= L_SEQ * D_INNER) return;
    int t = idx / D_INNER;
    int d = idx % D_INNER;

    float w0 = conv_w[d * 4 + 0], w1 = conv_w[d * 4 + 1];
    float w2 = conv_w[d * 4 + 2], w3 = conv_w[d * 4 + 3];

    float v = conv_b[d];
    const float* xc = g_xz + d;
    if (t >= 3) v = fmaf(w0, xc[(size_t)(t - 3) * 4096], v);
    if (t >= 2) v = fmaf(w1, xc[(size_t)(t - 2) * 4096], v);
    if (t >= 1) v = fmaf(w2, xc[(size_t)(t - 1) * 4096], v);
    v = fmaf(w3, xc[(size_t)t * 4096], v);

    float s = 1.f / (1.f + __expf(-v));
    g_xconv[idx] = v * s;
}

// ---------------- x_dbl = x_conv @ x_proj_w^T (N=96), emits fp32 + hi/lo ----------------
__global__ __launch_bounds__(256, 2)
void xproj_kernel(const float* __restrict__ x_proj_w)
{
    __shared__ float sX[32][65];
    __shared__ float sW[96][64];

    int tid = threadIdx.x;
    int t0 = blockIdx.x * 32;
    int tl = tid & 31;
    int jg = tid >> 5;

    float acc[12];
    #pragma unroll
    for (int i = 0; i < 12; i++) acc[i] = 0.f;

    for (int k0 = 0; k0 < D_INNER; k0 += 64) {
        for (int idx = tid; idx < 32 * 64; idx += 256) {
            int r = idx >> 6, c = idx & 63;
            sX[r][c] = g_xconv[(size_t)(t0 + r) * D_INNER + k0 + c];
        }
        for (int idx = tid; idx < 96 * 64; idx += 256) {
            int r = idx >> 6, c = idx & 63;
            sW[r][c] = x_proj_w[(size_t)r * D_INNER + k0 + c];
        }
        __syncthreads();

        #pragma unroll 8
        for (int k = 0; k < 64; k++) {
            float xv = sX[tl][k];
            #pragma unroll
            for (int i = 0; i < 12; i++)
                acc[i] = fmaf(xv, sW[jg + 8 * i][k], acc[i]);
        }
        __syncthreads();
    }

    #pragma unroll
    for (int i = 0; i < 12; i++) {
        size_t o = (size_t)(t0 + tl) * XPROJ + jg + 8 * i;
        float v = acc[i];
        g_xdbl[o] = v;
        __half h, l;
        split1(v, h, l);
        g_xdh[o] = h;
        g_xdl[o] = l;
    }
}

// ---------------- selective scan (emits u as fp16 hi/lo) ----------------
__global__ __launch_bounds__(256, 4)
void scan_kernel(const float* __restrict__ A_log,
                 const float* __restrict__ D_param)
{
    const int CHUNK = 128;
    __shared__ float s_BC[CHUNK][32];
    __shared__ float s_dt[CHUNK][16];
    __shared__ float s_x [CHUNK][16];
    __shared__ float s_y [CHUNK][16];

    int tid = threadIdx.x;
    int ld  = tid >> 4;
    int n   = tid & 15;
    int d0  = blockIdx.x * 16;
    int d   = d0 + ld;

    float Acoef = -__expf(A_log[(size_t)d * D_STATE + n]);
    float Dd    = D_param[d];
    float h = 0.f;

    for (int t0 = 0; t0 < L_SEQ; t0 += CHUNK) {
        for (int idx = tid; idx < CHUNK * 32; idx += 256) {
            int i = idx >> 5, c = idx & 31;
            s_BC[i][c] = g_xdbl[(size_t)(t0 + i) * XPROJ + 64 + c];
        }
        for (int idx = tid; idx < CHUNK * 16; idx += 256) {
            int i = idx >> 4, dd = idx & 15;
            size_t off = (size_t)(t0 + i) * D_INNER + d0 + dd;
            s_dt[i][dd] = g_dt[off];
            s_x [i][dd] = g_xconv[off];
        }
        __syncthreads();

        for (int i = 0; i < CHUNK; i++) {
            float dtv = s_dt[i][ld];
            float xv  = s_x [i][ld];
            float dA  = __expf(dtv * Acoef);
            h = fmaf(dA, h, dtv * xv * s_BC[i][n]);
            float yc = h * s_BC[i][16 + n];
            yc += __shfl_xor_sync(0xffffffffu, yc, 8, 16);
            yc += __shfl_xor_sync(0xffffffffu, yc, 4, 16);
            yc += __shfl_xor_sync(0xffffffffu, yc, 2, 16);
            yc += __shfl_xor_sync(0xffffffffu, yc, 1, 16);
            if (n == 0) s_y[i][ld] = fmaf(Dd, xv, yc);
        }
        __syncthreads();

        for (int idx = tid; idx < CHUNK * 16; idx += 256) {
            int i = idx >> 4, dd = idx & 15;
            int t = t0 + i, dcol = d0 + dd;
            float z = g_xz[(size_t)t * 4096 + 2048 + dcol];
            float sz = z / (1.f + __expf(-z));
            float u = s_y[i][dd] * sz;
            __half uh, ul;
            split1(u, uh, ul);
            size_t o = (size_t)t * D_INNER + dcol;
            g_uh[o] = uh;
            g_ul[o] = ul;
        }
        __syncthreads();
    }
}

// ---------------- launch ----------------
extern "C" void kernel_launch(void* const* d_in, const int* in_sizes, int n_in,
                              void* d_out, int out_size)
{
    const float* x         = (const float*)d_in[0];
    const float* in_proj_w = (const float*)d_in[1];
    const float* conv_w    = (const float*)d_in[2];
    const float* conv_b    = (const float*)d_in[3];
    const float* x_proj_w  = (const float*)d_in[4];
    const float* dt_proj_w = (const float*)d_in[5];
    const float* dt_proj_b = (const float*)d_in[6];
    const float* A_log     = (const float*)d_in[7];
    const float* D_param   = (const float*)d_in[8];
    const float* out_proj_w= (const float*)d_in[9];
    float* out = (float*)d_out;

    float *xz, *dt;
    cudaGetSymbolAddress((void**)&xz, g_xz);
    cudaGetSymbolAddress((void**)&dt, g_dt);

    __half *xh, *xl, *wih, *xdh, *xdl, *dwh, *uh, *ul, *owh;
    cudaGetSymbolAddress((void**)&xh,  g_xh);  cudaGetSymbolAddress((void**)&xl,  g_xl);
    cudaGetSymbolAddress((void**)&wih, g_wih);
    cudaGetSymbolAddress((void**)&xdh, g_xdh); cudaGetSymbolAddress((void**)&xdl, g_xdl);
    cudaGetSymbolAddress((void**)&dwh, g_dwh);
    cudaGetSymbolAddress((void**)&uh,  g_uh);  cudaGetSymbolAddress((void**)&ul,  g_ul);
    cudaGetSymbolAddress((void**)&owh, g_owh);

    cudaFuncSetAttribute(mma_gemm<0>, cudaFuncAttributeMaxDynamicSharedMemorySize, DSMEM_BYTES);
    cudaFuncSetAttribute(mma_gemm<1>, cudaFuncAttributeMaxDynamicSharedMemorySize, DSMEM_BYTES);

    const int ST = 256;
    // launches 0..2: splits (out_proj_w hoisted so GEMM1 is launch #3 = profiled slot)
    split_f16<<<(L_SEQ * D_MODEL + ST - 1) / ST, ST>>>(x, xh, xl, L_SEQ * D_MODEL);
    split_f16<<<(2 * D_INNER * D_MODEL + ST - 1) / ST, ST>>>(in_proj_w, wih, nullptr, 2 * D_INNER * D_MODEL);
    split_f16<<<(D_MODEL * D_INNER + ST - 1) / ST, ST>>>(out_proj_w, owh, nullptr, D_MODEL * D_INNER);

    // 3) xz = x @ in_proj_w^T : (2048, 4096)
    {
        dim3 grid(4096 / 128, 2048 / 128);
        mma_gemm<0><<<grid, 256, DSMEM_BYTES>>>(2048, 4096, 1024,
            xh, xl, 1024, wih, 1024, xz, 4096, nullptr);
    }
    // 4) conv + SiLU
    conv_silu_kernel<<<(L_SEQ * D_INNER + ST - 1) / ST, ST>>>(conv_w, conv_b);
    // 5) x_dbl (+ inline hi/lo split)
    xproj_kernel<<<L_SEQ / 32, 256>>>(x_proj_w);
    // 6) dt weights split
    split_f16<<<(D_INNER * DT_RANK + ST - 1) / ST, ST>>>(dt_proj_w, dwh, nullptr, D_INNER * DT_RANK);
    // 7) dt = softplus(x_dbl[:, :64] @ dt_proj_w^T + b)
    {
        dim3 grid(2048 / 128, 2048 / 128);
        mma_gemm<1><<<grid, 256, DSMEM_BYTES>>>(2048, 2048, 64,
            xdh, xdl, XPROJ, dwh, DT_RANK, dt, 2048, dt_proj_b);
    }
    // 8) scan (+ inline u hi/lo split)
    scan_kernel<<<D_INNER / 16, 256>>>(A_log, D_param);
    // 9) out = u @ out_proj_w^T
    {
        dim3 grid(1024 / 128, 2048 / 128);
        mma_gemm<0><<<grid, 256, DSMEM_BYTES>>>(2048, 1024, 2048,
            uh, ul, 2048, owh, 2048, out, 1024, nullptr);
    }
}

// round 6
// speedup vs baseline: 1.9455x; 1.1049x over previous
#include <cuda_runtime.h>
#include <cuda_fp16.h>
#include <cstdint>

// ---------------- problem constants ----------------
#define L_SEQ   2048
#define D_MODEL 1024
#define D_INNER 2048
#define D_STATE 16
#define DT_RANK 64
#define XPROJ   96
#define D_CONV  4

// ---------------- fp32 scratch ----------------
__device__ float g_xz   [L_SEQ * 2 * D_INNER];
__device__ float g_xconv[L_SEQ * D_INNER];
__device__ float g_xdbl [L_SEQ * XPROJ];
__device__ float g_dt   [L_SEQ * D_INNER];

// ---------------- fp16 hi/lo scratch ----------------
__device__ __half g_xh [L_SEQ * D_MODEL],      g_xl [L_SEQ * D_MODEL];
__device__ __half g_wih[2*D_INNER * D_MODEL];
__device__ __half g_xdh[L_SEQ * XPROJ],        g_xdl[L_SEQ * XPROJ];
__device__ __half g_dwh[D_INNER * DT_RANK];
__device__ __half g_uh [L_SEQ * D_INNER],      g_ul [L_SEQ * D_INNER];
__device__ __half g_owh[D_MODEL * D_INNER];

// ================= helpers =================
__device__ __forceinline__ uint32_t smem_u32(const void* p) {
    uint32_t a;
    asm("{ .reg .u64 t; cvta.to.shared.u64 t, %1; cvt.u32.u64 %0, t; }" : "=r"(a) : "l"(p));
    return a;
}
__device__ __forceinline__ void cp16(uint32_t dst, const void* src) {
    asm volatile("cp.async.cg.shared.global [%0], [%1], 16;" :: "r"(dst), "l"(src));
}
__device__ __forceinline__ void cp_commit() {
    asm volatile("cp.async.commit_group;" ::: "memory");
}
__device__ __forceinline__ void cp_wait0() {
    asm volatile("cp.async.wait_group 0;" ::: "memory");
}
__device__ __forceinline__ void ldmat4(uint32_t* r, uint32_t addr) {
    asm volatile("ldmatrix.sync.aligned.m8n8.x4.shared.b16 {%0,%1,%2,%3}, [%4];"
                 : "=r"(r[0]), "=r"(r[1]), "=r"(r[2]), "=r"(r[3]) : "r"(addr));
}
__device__ __forceinline__ void mma_f16(float* d, const uint32_t* a, const uint32_t* b) {
    asm volatile("mma.sync.aligned.m16n8k16.row.col.f32.f16.f16.f32 "
                 "{%0,%1,%2,%3}, {%4,%5,%6,%7}, {%8,%9}, {%0,%1,%2,%3};"
                 : "+f"(d[0]), "+f"(d[1]), "+f"(d[2]), "+f"(d[3])
                 : "r"(a[0]), "r"(a[1]), "r"(a[2]), "r"(a[3]), "r"(b[0]), "r"(b[1]));
}
__device__ __forceinline__ void split1(float v, __half& h, __half& l) {
    h = __float2half_rn(v);
    l = __float2half_rn(v - __half2float(h));
}

// ================= fp32 -> fp16 hi/lo split =================
__global__ void split_f16(const float* __restrict__ in,
                          __half* __restrict__ hi,
                          __half* __restrict__ lo, int n)
{
    int i = blockIdx.x * blockDim.x + threadIdx.x;
    if (i >= n) return;
    float v = in[i];
    __half h, l;
    split1(v, h, l);
    hi[i] = h;
    if (lo) lo[i] = l;
}

// ================= split-fp16 HMMA GEMM =================
#define TILE_B   10240
#define STAGE_B  30720
#define DSMEM_BYTES (2 * STAGE_B)

__device__ __forceinline__ void load_stage(
    uint32_t st, const __half* Ah, const __half* Al, int lda,
    const __half* Bh, int ldb, int m0, int n0, int k0, int tid)
{
    #pragma unroll
    for (int j = 0; j < 2; j++) {
        int cl = tid * 2 + j;
        int r  = cl >> 2;
        int cc = cl & 3;
        uint32_t so = (uint32_t)(r * 80 + cc * 16);
        size_t goA = (size_t)(m0 + r) * lda + k0 + cc * 8;
        size_t goB = (size_t)(n0 + r) * ldb + k0 + cc * 8;
        cp16(st + so,              Ah + goA);
        cp16(st + TILE_B + so,     Al + goA);
        cp16(st + 2 * TILE_B + so, Bh + goB);
    }
    cp_commit();
}

template <int EPI>
__global__ __launch_bounds__(256, 2)
void mma_gemm(int M, int N, int K,
              const __half* __restrict__ Ah, const __half* __restrict__ Al, int lda,
              const __half* __restrict__ Bh, int ldb,
              float* __restrict__ C, int ldc, const float* __restrict__ bias)
{
    extern __shared__ char smem[];
    uint32_t sbase = smem_u32(smem);

    int tid = threadIdx.x;
    int lane = tid & 31, wid = tid >> 5;
    int warp_m = wid & 3, warp_n = wid >> 2;
    int m0 = blockIdx.y * 128, n0 = blockIdx.x * 128;

    float acc[2][8][4];
    #pragma unroll
    for (int i = 0; i < 2; i++)
        #pragma unroll
        for (int j = 0; j < 8; j++)
            #pragma unroll
            for (int q = 0; q < 4; q++) acc[i][j][q] = 0.f;

    uint32_t a_off = (uint32_t)((warp_m * 32 + (lane & 15)) * 80 + (lane >> 4) * 16);
    uint32_t b_off = (uint32_t)((warp_n * 64 + ((lane & 7) | ((lane & 16) >> 1))) * 80
                                + ((lane >> 3) & 1) * 16);

    int NK = K >> 5;
    load_stage(sbase, Ah, Al, lda, Bh, ldb, m0, n0, 0, tid);

    for (int kc = 0; kc < NK; kc++) {
        cp_wait0();
        __syncthreads();
        if (kc + 1 < NK)
            load_stage(sbase + ((kc + 1) & 1) * STAGE_B,
                       Ah, Al, lda, Bh, ldb, m0, n0, (kc + 1) * 32, tid);

        uint32_t st = sbase + (kc & 1) * STAGE_B;
        #pragma unroll
        for (int ks = 0; ks < 2; ks++) {
            uint32_t ah[2][4], al[2][4];
            ldmat4(ah[0], st + a_off + ks * 32);
            ldmat4(ah[1], st + a_off + 1280 + ks * 32);
            ldmat4(al[0], st + TILE_B + a_off + ks * 32);
            ldmat4(al[1], st + TILE_B + a_off + 1280 + ks * 32);

            #pragma unroll
            for (int half = 0; half < 2; half++) {
                uint32_t b[4][2];
                #pragma unroll
                for (int nj = 0; nj < 2; nj++) {
                    uint32_t r4[4];
                    ldmat4(r4, st + 2 * TILE_B + b_off + (half * 2 + nj) * 1280 + ks * 32);
                    b[2*nj][0] = r4[0]; b[2*nj][1] = r4[1];
                    b[2*nj+1][0] = r4[2]; b[2*nj+1][1] = r4[3];
                }
                #pragma unroll
                for (int mi = 0; mi < 2; mi++)
                    #pragma unroll
                    for (int ni = 0; ni < 4; ni++)
                        mma_f16(acc[mi][half * 4 + ni], ah[mi], b[ni]);
                #pragma unroll
                for (int mi = 0; mi < 2; mi++)
                    #pragma unroll
                    for (int ni = 0; ni < 4; ni++)
                        mma_f16(acc[mi][half * 4 + ni], al[mi], b[ni]);
            }
        }
        __syncthreads();
    }

    int gr = lane >> 2, gc = (lane & 3) * 2;
    int row_base = m0 + warp_m * 32;
    int col_base = n0 + warp_n * 64;
    #pragma unroll
    for (int mi = 0; mi < 2; mi++) {
        #pragma unroll
        for (int ni = 0; ni < 8; ni++) {
            int r0 = row_base + mi * 16 + gr;
            int c  = col_base + ni * 8 + gc;
            float v0 = acc[mi][ni][0], v1 = acc[mi][ni][1];
            float v2 = acc[mi][ni][2], v3 = acc[mi][ni][3];
            if (EPI == 1) {
                float b0 = bias[c], b1 = bias[c + 1];
                v0 += b0; v1 += b1; v2 += b0; v3 += b1;
                v0 = (v0 > 20.f) ? v0 : log1pf(__expf(v0));
                v1 = (v1 > 20.f) ? v1 : log1pf(__expf(v1));
                v2 = (v2 > 20.f) ? v2 : log1pf(__expf(v2));
                v3 = (v3 > 20.f) ? v3 : log1pf(__expf(v3));
            }
            *(float2*)(C + (size_t)r0 * ldc + c)       = make_float2(v0, v1);
            *(float2*)(C + (size_t)(r0 + 8) * ldc + c) = make_float2(v2, v3);
        }
    }
}

// ---------------- depthwise causal conv (k=4) + bias + SiLU ----------------
__global__ void conv_silu_kernel(const float* __restrict__ conv_w,
                                 const float* __restrict__ conv_b)
{
    int idx = blockIdx.x * blockDim.x + threadIdx.x;
    if (idx >= L_SEQ * D_INNER) return;
    int t = idx / D_INNER;
    int d = idx % D_INNER;

    float w0 = conv_w[d * 4 + 0], w1 = conv_w[d * 4 + 1];
    float w2 = conv_w[d * 4 + 2], w3 = conv_w[d * 4 + 3];

    float v = conv_b[d];
    const float* xc = g_xz + d;
    if (t >= 3) v = fmaf(w0, xc[(size_t)(t - 3) * 4096], v);
    if (t >= 2) v = fmaf(w1, xc[(size_t)(t - 2) * 4096], v);
    if (t >= 1) v = fmaf(w2, xc[(size_t)(t - 1) * 4096], v);
    v = fmaf(w3, xc[(size_t)t * 4096], v);

    float s = 1.f / (1.f + __expf(-v));
    g_xconv[idx] = v * s;
}

// ---------------- x_dbl = x_conv @ x_proj_w^T (N=96), emits fp32 + hi/lo ----------------
__global__ __launch_bounds__(256, 2)
void xproj_kernel(const float* __restrict__ x_proj_w)
{
    __shared__ float sX[32][65];
    __shared__ float sW[96][64];

    int tid = threadIdx.x;
    int t0 = blockIdx.x * 32;
    int tl = tid & 31;
    int jg = tid >> 5;

    float acc[12];
    #pragma unroll
    for (int i = 0; i < 12; i++) acc[i] = 0.f;

    for (int k0 = 0; k0 < D_INNER; k0 += 64) {
        for (int idx = tid; idx < 32 * 64; idx += 256) {
            int r = idx >> 6, c = idx & 63;
            sX[r][c] = g_xconv[(size_t)(t0 + r) * D_INNER + k0 + c];
        }
        for (int idx = tid; idx < 96 * 64; idx += 256) {
            int r = idx >> 6, c = idx & 63;
            sW[r][c] = x_proj_w[(size_t)r * D_INNER + k0 + c];
        }
        __syncthreads();

        #pragma unroll 8
        for (int k = 0; k < 64; k++) {
            float xv = sX[tl][k];
            #pragma unroll
            for (int i = 0; i < 12; i++)
                acc[i] = fmaf(xv, sW[jg + 8 * i][k], acc[i]);
        }
        __syncthreads();
    }

    #pragma unroll
    for (int i = 0; i < 12; i++) {
        size_t o = (size_t)(t0 + tl) * XPROJ + jg + 8 * i;
        float v = acc[i];
        g_xdbl[o] = v;
        __half h, l;
        split1(v, h, l);
        g_xdh[o] = h;
        g_xdl[o] = l;
    }
}

// ---------------- selective scan (4x unrolled, batched reductions) ----------------
// block = 128 threads: 8 d-channels x 16 states; 256 blocks cover D_INNER.
__global__ __launch_bounds__(128, 8)
void scan_kernel(const float* __restrict__ A_log,
                 const float* __restrict__ D_param)
{
    const int CHUNK = 64;
    __shared__ float s_BC[CHUNK][32];   // [..,0:16)=B, [..,16:32)=C
    __shared__ float s_dt[CHUNK][8];
    __shared__ float s_x [CHUNK][8];
    __shared__ float s_y [CHUNK][8];

    int tid = threadIdx.x;
    int ld  = tid >> 4;                 // local d, 0..7
    int n   = tid & 15;                 // state index
    int d0  = blockIdx.x * 8;
    int d   = d0 + ld;

    float Acoef = -__expf(A_log[(size_t)d * D_STATE + n]);
    float Dd    = D_param[d];
    float h = 0.f;

    for (int t0 = 0; t0 < L_SEQ; t0 += CHUNK) {
        // stage B,C (columns 64..95 of x_dbl)
        for (int idx = tid; idx < CHUNK * 32; idx += 128) {
            int i = idx >> 5, c = idx & 31;
            s_BC[i][c] = g_xdbl[(size_t)(t0 + i) * XPROJ + 64 + c];
        }
        // stage dt, x_conv
        for (int idx = tid; idx < CHUNK * 8; idx += 128) {
            int i = idx >> 3, dd = idx & 7;
            size_t off = (size_t)(t0 + i) * D_INNER + d0 + dd;
            s_dt[i][dd] = g_dt[off];
            s_x [i][dd] = g_xconv[off];
        }
        __syncthreads();

        for (int i = 0; i < CHUNK; i += 4) {
            float dAv[4], dbx[4], cv[4], xv[4], ya[4];
            #pragma unroll
            for (int j = 0; j < 4; j++) {
                float dtv = s_dt[i + j][ld];
                xv[j]  = s_x[i + j][ld];
                dAv[j] = __expf(dtv * Acoef);
                dbx[j] = dtv * xv[j] * s_BC[i + j][n];
                cv[j]  = s_BC[i + j][16 + n];
            }
            // serial h-chain (cheap: 4 fma + 4 mul)
            #pragma unroll
            for (int j = 0; j < 4; j++) {
                h = fmaf(dAv[j], h, dbx[j]);
                ya[j] = h * cv[j];
            }
            // 4 interleaved reduction trees over the 16 state lanes
            #pragma unroll
            for (int off = 8; off; off >>= 1) {
                #pragma unroll
                for (int j = 0; j < 4; j++)
                    ya[j] += __shfl_xor_sync(0xffffffffu, ya[j], off, 16);
            }
            if (n == 0) {
                #pragma unroll
                for (int j = 0; j < 4; j++)
                    s_y[i + j][ld] = fmaf(Dd, xv[j], ya[j]);
            }
        }
        __syncthreads();

        // u = y * silu(z), emit fp16 hi/lo
        for (int idx = tid; idx < CHUNK * 8; idx += 128) {
            int i = idx >> 3, dd = idx & 7;
            int t = t0 + i, dcol = d0 + dd;
            float z = g_xz[(size_t)t * 4096 + 2048 + dcol];
            float sz = z / (1.f + __expf(-z));
            float u = s_y[i][dd] * sz;
            __half uh, ul;
            split1(u, uh, ul);
            size_t o = (size_t)t * D_INNER + dcol;
            g_uh[o] = uh;
            g_ul[o] = ul;
        }
        __syncthreads();
    }
}

// ---------------- launch ----------------
extern "C" void kernel_launch(void* const* d_in, const int* in_sizes, int n_in,
                              void* d_out, int out_size)
{
    const float* x         = (const float*)d_in[0];
    const float* in_proj_w = (const float*)d_in[1];
    const float* conv_w    = (const float*)d_in[2];
    const float* conv_b    = (const float*)d_in[3];
    const float* x_proj_w  = (const float*)d_in[4];
    const float* dt_proj_w = (const float*)d_in[5];
    const float* dt_proj_b = (const float*)d_in[6];
    const float* A_log     = (const float*)d_in[7];
    const float* D_param   = (const float*)d_in[8];
    const float* out_proj_w= (const float*)d_in[9];
    float* out = (float*)d_out;

    float *xz, *dt;
    cudaGetSymbolAddress((void**)&xz, g_xz);
    cudaGetSymbolAddress((void**)&dt, g_dt);

    __half *xh, *xl, *wih, *xdh, *xdl, *dwh, *uh, *ul, *owh;
    cudaGetSymbolAddress((void**)&xh,  g_xh);  cudaGetSymbolAddress((void**)&xl,  g_xl);
    cudaGetSymbolAddress((void**)&wih, g_wih);
    cudaGetSymbolAddress((void**)&xdh, g_xdh); cudaGetSymbolAddress((void**)&xdl, g_xdl);
    cudaGetSymbolAddress((void**)&dwh, g_dwh);
    cudaGetSymbolAddress((void**)&uh,  g_uh);  cudaGetSymbolAddress((void**)&ul,  g_ul);
    cudaGetSymbolAddress((void**)&owh, g_owh);

    cudaFuncSetAttribute(mma_gemm<0>, cudaFuncAttributeMaxDynamicSharedMemorySize, DSMEM_BYTES);
    cudaFuncSetAttribute(mma_gemm<1>, cudaFuncAttributeMaxDynamicSharedMemorySize, DSMEM_BYTES);

    const int ST = 256;
    split_f16<<<(L_SEQ * D_MODEL + ST - 1) / ST, ST>>>(x, xh, xl, L_SEQ * D_MODEL);
    split_f16<<<(2 * D_INNER * D_MODEL + ST - 1) / ST, ST>>>(in_proj_w, wih, nullptr, 2 * D_INNER * D_MODEL);
    split_f16<<<(D_MODEL * D_INNER + ST - 1) / ST, ST>>>(out_proj_w, owh, nullptr, D_MODEL * D_INNER);

    // 3) xz = x @ in_proj_w^T : (2048, 4096)
    {
        dim3 grid(4096 / 128, 2048 / 128);
        mma_gemm<0><<<grid, 256, DSMEM_BYTES>>>(2048, 4096, 1024,
            xh, xl, 1024, wih, 1024, xz, 4096, nullptr);
    }
    // 4) conv + SiLU
    conv_silu_kernel<<<(L_SEQ * D_INNER + ST - 1) / ST, ST>>>(conv_w, conv_b);
    // 5) x_dbl (+ inline hi/lo split)
    xproj_kernel<<<L_SEQ / 32, 256>>>(x_proj_w);
    // 6) dt weights split
    split_f16<<<(D_INNER * DT_RANK + ST - 1) / ST, ST>>>(dt_proj_w, dwh, nullptr, D_INNER * DT_RANK);
    // 7) dt = softplus(x_dbl[:, :64] @ dt_proj_w^T + b)
    {
        dim3 grid(2048 / 128, 2048 / 128);
        mma_gemm<1><<<grid, 256, DSMEM_BYTES>>>(2048, 2048, 64,
            xdh, xdl, XPROJ, dwh, DT_RANK, dt, 2048, dt_proj_b);
    }
    // 8) scan (+ inline u hi/lo split)
    scan_kernel<<<D_INNER / 8, 128>>>(A_log, D_param);
    // 9) out = u @ out_proj_w^T
    {
        dim3 grid(1024 / 128, 2048 / 128);
        mma_gemm<0><<<grid, 256, DSMEM_BYTES>>>(2048, 1024, 2048,
            uh, ul, 2048, owh, 2048, out, 1024, nullptr);
    }
}

// round 7
// speedup vs baseline: 2.3055x; 1.1850x over previous
#include <cuda_runtime.h>
#include <cuda_fp16.h>
#include <cstdint>

// ---------------- problem constants ----------------
#define L_SEQ   2048
#define D_MODEL 1024
#define D_INNER 2048
#define D_STATE 16
#define DT_RANK 64
#define XPROJ   96
#define D_CONV  4
#define NCHUNK  16
#define CLEN    128     // L_SEQ / NCHUNK

// ---------------- fp32 scratch ----------------
__device__ float g_xz   [L_SEQ * 2 * D_INNER];
__device__ float g_xconv[L_SEQ * D_INNER];
__device__ float g_xdbl [L_SEQ * XPROJ];
__device__ float g_dt   [L_SEQ * D_INNER];
// scan chunk summaries: indexed ((d*16+n)*NCHUNK + c)
__device__ float g_hend [D_INNER * D_STATE * NCHUNK];
__device__ float g_decay[D_INNER * D_STATE * NCHUNK];
__device__ float g_hinit[D_INNER * D_STATE * NCHUNK];

// ---------------- fp16 hi/lo scratch ----------------
__device__ __half g_xh [L_SEQ * D_MODEL],      g_xl [L_SEQ * D_MODEL];
__device__ __half g_wih[2*D_INNER * D_MODEL];
__device__ __half g_xdh[L_SEQ * XPROJ],        g_xdl[L_SEQ * XPROJ];
__device__ __half g_dwh[D_INNER * DT_RANK];
__device__ __half g_uh [L_SEQ * D_INNER],      g_ul [L_SEQ * D_INNER];
__device__ __half g_owh[D_MODEL * D_INNER];

// ================= helpers =================
__device__ __forceinline__ uint32_t smem_u32(const void* p) {
    uint32_t a;
    asm("{ .reg .u64 t; cvta.to.shared.u64 t, %1; cvt.u32.u64 %0, t; }" : "=r"(a) : "l"(p));
    return a;
}
__device__ __forceinline__ void cp16(uint32_t dst, const void* src) {
    asm volatile("cp.async.cg.shared.global [%0], [%1], 16;" :: "r"(dst), "l"(src));
}
__device__ __forceinline__ void cp_commit() {
    asm volatile("cp.async.commit_group;" ::: "memory");
}
__device__ __forceinline__ void cp_wait0() {
    asm volatile("cp.async.wait_group 0;" ::: "memory");
}
__device__ __forceinline__ void ldmat4(uint32_t* r, uint32_t addr) {
    asm volatile("ldmatrix.sync.aligned.m8n8.x4.shared.b16 {%0,%1,%2,%3}, [%4];"
                 : "=r"(r[0]), "=r"(r[1]), "=r"(r[2]), "=r"(r[3]) : "r"(addr));
}
__device__ __forceinline__ void mma_f16(float* d, const uint32_t* a, const uint32_t* b) {
    asm volatile("mma.sync.aligned.m16n8k16.row.col.f32.f16.f16.f32 "
                 "{%0,%1,%2,%3}, {%4,%5,%6,%7}, {%8,%9}, {%0,%1,%2,%3};"
                 : "+f"(d[0]), "+f"(d[1]), "+f"(d[2]), "+f"(d[3])
                 : "r"(a[0]), "r"(a[1]), "r"(a[2]), "r"(a[3]), "r"(b[0]), "r"(b[1]));
}
__device__ __forceinline__ void split1(float v, __half& h, __half& l) {
    h = __float2half_rn(v);
    l = __float2half_rn(v - __half2float(h));
}

// ================= fp32 -> fp16 hi/lo split =================
__global__ void split_f16(const float* __restrict__ in,
                          __half* __restrict__ hi,
                          __half* __restrict__ lo, int n)
{
    int i = blockIdx.x * blockDim.x + threadIdx.x;
    if (i >= n) return;
    float v = in[i];
    __half h, l;
    split1(v, h, l);
    hi[i] = h;
    if (lo) lo[i] = l;
}

// ================= split-fp16 HMMA GEMM (templated BM = 64*MI) =================
template <int MI>
__device__ __forceinline__ void load_stage(
    uint32_t st, const __half* Ah, const __half* Al, int lda,
    const __half* Bh, int ldb, int m0, int n0, int k0, int tid)
{
    constexpr int TA = 64 * MI * 80;   // bytes per A tile
    #pragma unroll
    for (int j = 0; j < 2; j++) {
        int cl = tid * 2 + j;
        int r  = cl >> 2;
        int cc = cl & 3;
        uint32_t so = (uint32_t)(r * 80 + cc * 16);
        size_t goB = (size_t)(n0 + r) * ldb + k0 + cc * 8;
        if (MI == 2 || r < 64) {
            size_t goA = (size_t)(m0 + r) * lda + k0 + cc * 8;
            cp16(st + so,      Ah + goA);
            cp16(st + TA + so, Al + goA);
        }
        cp16(st + 2 * TA + so, Bh + goB);
    }
    cp_commit();
}

template <int EPI, int MI>
__global__ __launch_bounds__(256, 2)
void mma_gemm(int M, int N, int K,
              const __half* __restrict__ Ah, const __half* __restrict__ Al, int lda,
              const __half* __restrict__ Bh, int ldb,
              float* __restrict__ C, int ldc, const float* __restrict__ bias)
{
    constexpr int BM    = 64 * MI;
    constexpr int TA    = BM * 80;
    constexpr int STAGE = 2 * TA + 10240;

    extern __shared__ char smem[];
    uint32_t sbase = smem_u32(smem);

    int tid = threadIdx.x;
    int lane = tid & 31, wid = tid >> 5;
    int warp_m = wid & 3, warp_n = wid >> 2;
    int m0 = blockIdx.y * BM, n0 = blockIdx.x * 128;

    float acc[MI][8][4];
    #pragma unroll
    for (int i = 0; i < MI; i++)
        #pragma unroll
        for (int j = 0; j < 8; j++)
            #pragma unroll
            for (int q = 0; q < 4; q++) acc[i][j][q] = 0.f;

    uint32_t a_off = (uint32_t)((warp_m * 16 * MI + (lane & 15)) * 80 + (lane >> 4) * 16);
    uint32_t b_off = (uint32_t)((warp_n * 64 + ((lane & 7) | ((lane & 16) >> 1))) * 80
                                + ((lane >> 3) & 1) * 16);

    int NK = K >> 5;
    load_stage<MI>(sbase, Ah, Al, lda, Bh, ldb, m0, n0, 0, tid);

    for (int kc = 0; kc < NK; kc++) {
        cp_wait0();
        __syncthreads();
        if (kc + 1 < NK)
            load_stage<MI>(sbase + ((kc + 1) & 1) * STAGE,
                           Ah, Al, lda, Bh, ldb, m0, n0, (kc + 1) * 32, tid);

        uint32_t st = sbase + (kc & 1) * STAGE;
        #pragma unroll
        for (int ks = 0; ks < 2; ks++) {
            uint32_t ah[MI][4], al[MI][4];
            #pragma unroll
            for (int mi = 0; mi < MI; mi++) {
                ldmat4(ah[mi], st + a_off + mi * 1280 + ks * 32);
                ldmat4(al[mi], st + TA + a_off + mi * 1280 + ks * 32);
            }
            #pragma unroll
            for (int half = 0; half < 2; half++) {
                uint32_t b[4][2];
                #pragma unroll
                for (int nj = 0; nj < 2; nj++) {
                    uint32_t r4[4];
                    ldmat4(r4, st + 2 * TA + b_off + (half * 2 + nj) * 1280 + ks * 32);
                    b[2*nj][0] = r4[0]; b[2*nj][1] = r4[1];
                    b[2*nj+1][0] = r4[2]; b[2*nj+1][1] = r4[3];
                }
                #pragma unroll
                for (int mi = 0; mi < MI; mi++)
                    #pragma unroll
                    for (int ni = 0; ni < 4; ni++)
                        mma_f16(acc[mi][half * 4 + ni], ah[mi], b[ni]);
                #pragma unroll
                for (int mi = 0; mi < MI; mi++)
                    #pragma unroll
                    for (int ni = 0; ni < 4; ni++)
                        mma_f16(acc[mi][half * 4 + ni], al[mi], b[ni]);
            }
        }
        __syncthreads();
    }

    int gr = lane >> 2, gc = (lane & 3) * 2;
    int row_base = m0 + warp_m * 16 * MI;
    int col_base = n0 + warp_n * 64;
    #pragma unroll
    for (int mi = 0; mi < MI; mi++) {
        #pragma unroll
        for (int ni = 0; ni < 8; ni++) {
            int r0 = row_base + mi * 16 + gr;
            int c  = col_base + ni * 8 + gc;
            float v0 = acc[mi][ni][0], v1 = acc[mi][ni][1];
            float v2 = acc[mi][ni][2], v3 = acc[mi][ni][3];
            if (EPI == 1) {
                float b0 = bias[c], b1 = bias[c + 1];
                v0 += b0; v1 += b1; v2 += b0; v3 += b1;
                v0 = (v0 > 20.f) ? v0 : log1pf(__expf(v0));
                v1 = (v1 > 20.f) ? v1 : log1pf(__expf(v1));
                v2 = (v2 > 20.f) ? v2 : log1pf(__expf(v2));
                v3 = (v3 > 20.f) ? v3 : log1pf(__expf(v3));
            }
            *(float2*)(C + (size_t)r0 * ldc + c)       = make_float2(v0, v1);
            *(float2*)(C + (size_t)(r0 + 8) * ldc + c) = make_float2(v2, v3);
        }
    }
}

// ---------------- depthwise causal conv (k=4) + bias + SiLU ----------------
__global__ void conv_silu_kernel(const float* __restrict__ conv_w,
                                 const float* __restrict__ conv_b)
{
    int idx = blockIdx.x * blockDim.x + threadIdx.x;
    if (idx >= L_SEQ * D_INNER) return;
    int t = idx / D_INNER;
    int d = idx % D_INNER;

    float w0 = conv_w[d * 4 + 0], w1 = conv_w[d * 4 + 1];
    float w2 = conv_w[d * 4 + 2], w3 = conv_w[d * 4 + 3];

    float v = conv_b[d];
    const float* xc = g_xz + d;
    if (t >= 3) v = fmaf(w0, xc[(size_t)(t - 3) * 4096], v);
    if (t >= 2) v = fmaf(w1, xc[(size_t)(t - 2) * 4096], v);
    if (t >= 1) v = fmaf(w2, xc[(size_t)(t - 1) * 4096], v);
    v = fmaf(w3, xc[(size_t)t * 4096], v);

    float s = 1.f / (1.f + __expf(-v));
    g_xconv[idx] = v * s;
}

// ---------------- x_dbl = x_conv @ x_proj_w^T (N=96), emits fp32 + hi/lo ----------------
__global__ __launch_bounds__(256, 2)
void xproj_kernel(const float* __restrict__ x_proj_w)
{
    __shared__ float sX[32][65];
    __shared__ float sW[96][64];

    int tid = threadIdx.x;
    int t0 = blockIdx.x * 32;
    int tl = tid & 31;
    int jg = tid >> 5;

    float acc[12];
    #pragma unroll
    for (int i = 0; i < 12; i++) acc[i] = 0.f;

    for (int k0 = 0; k0 < D_INNER; k0 += 64) {
        for (int idx = tid; idx < 32 * 64; idx += 256) {
            int r = idx >> 6, c = idx & 63;
            sX[r][c] = g_xconv[(size_t)(t0 + r) * D_INNER + k0 + c];
        }
        for (int idx = tid; idx < 96 * 64; idx += 256) {
            int r = idx >> 6, c = idx & 63;
            sW[r][c] = x_proj_w[(size_t)r * D_INNER + k0 + c];
        }
        __syncthreads();

        #pragma unroll 8
        for (int k = 0; k < 64; k++) {
            float xv = sX[tl][k];
            #pragma unroll
            for (int i = 0; i < 12; i++)
                acc[i] = fmaf(xv, sW[jg + 8 * i][k], acc[i]);
        }
        __syncthreads();
    }

    #pragma unroll
    for (int i = 0; i < 12; i++) {
        size_t o = (size_t)(t0 + tl) * XPROJ + jg + 8 * i;
        float v = acc[i];
        g_xdbl[o] = v;
        __half h, l;
        split1(v, h, l);
        g_xdh[o] = h;
        g_xdl[o] = l;
    }
}

// ---------------- scan pass 1: per-chunk partials ----------------
// grid (D_INNER/8, NCHUNK), block 128 (8 d x 16 n)
__global__ __launch_bounds__(128, 8)
void scan_part1(const float* __restrict__ A_log)
{
    const int SC = 64;
    __shared__ float s_B [SC][16];
    __shared__ float s_dt[SC][8];
    __shared__ float s_x [SC][8];

    int tid = threadIdx.x;
    int ld  = tid >> 4;
    int n   = tid & 15;
    int d0  = blockIdx.x * 8;
    int d   = d0 + ld;
    int c   = blockIdx.y;
    int tbase = c * CLEN;

    float Acoef = -__expf(A_log[(size_t)d * D_STATE + n]);
    float h = 0.f, sdt = 0.f;

    for (int t0 = tbase; t0 < tbase + CLEN; t0 += SC) {
        for (int idx = tid; idx < SC * 16; idx += 128) {
            int i = idx >> 4, cc = idx & 15;
            s_B[i][cc] = g_xdbl[(size_t)(t0 + i) * XPROJ + 64 + cc];
        }
        for (int idx = tid; idx < SC * 8; idx += 128) {
            int i = idx >> 3, dd = idx & 7;
            size_t off = (size_t)(t0 + i) * D_INNER + d0 + dd;
            s_dt[i][dd] = g_dt[off];
            s_x [i][dd] = g_xconv[off];
        }
        __syncthreads();

        for (int i = 0; i < SC; i += 4) {
            float dAv[4], dbx[4];
            #pragma unroll
            for (int j = 0; j < 4; j++) {
                float dtv = s_dt[i + j][ld];
                float xv  = s_x [i + j][ld];
                sdt += dtv;
                dAv[j] = __expf(dtv * Acoef);
                dbx[j] = dtv * xv * s_B[i + j][n];
            }
            #pragma unroll
            for (int j = 0; j < 4; j++)
                h = fmaf(dAv[j], h, dbx[j]);
        }
        __syncthreads();
    }

    size_t o = ((size_t)d * D_STATE + n) * NCHUNK + c;
    g_hend [o] = h;
    g_decay[o] = __expf(Acoef * sdt);
}

// ---------------- scan pass 2: combine chunk summaries ----------------
__global__ void scan_combine()
{
    int idx = blockIdx.x * blockDim.x + threadIdx.x;   // 0 .. 32767
    if (idx >= D_INNER * D_STATE) return;
    const float4* dec4 = (const float4*)(g_decay + (size_t)idx * NCHUNK);
    const float4* he4  = (const float4*)(g_hend  + (size_t)idx * NCHUNK);
    float4* hi4        = (float4*)(g_hinit + (size_t)idx * NCHUNK);
    float h = 0.f;
    #pragma unroll
    for (int q = 0; q < NCHUNK / 4; q++) {
        float4 dc = dec4[q], he = he4[q], out;
        out.x = h; h = fmaf(dc.x, h, he.x);
        out.y = h; h = fmaf(dc.y, h, he.y);
        out.z = h; h = fmaf(dc.z, h, he.z);
        out.w = h; h = fmaf(dc.w, h, he.w);
        hi4[q] = out;
    }
}

// ---------------- scan pass 3: full scan per chunk with y + u ----------------
// grid (D_INNER/8, NCHUNK), block 128
__global__ __launch_bounds__(128, 8)
void scan_part3(const float* __restrict__ A_log,
                const float* __restrict__ D_param)
{
    const int SC = 64;
    __shared__ float s_BC[SC][32];
    __shared__ float s_dt[SC][8];
    __shared__ float s_x [SC][8];
    __shared__ float s_y [SC][8];

    int tid = threadIdx.x;
    int ld  = tid >> 4;
    int n   = tid & 15;
    int d0  = blockIdx.x * 8;
    int d   = d0 + ld;
    int c   = blockIdx.y;
    int tbase = c * CLEN;

    float Acoef = -__expf(A_log[(size_t)d * D_STATE + n]);
    float Dd    = D_param[d];
    float h = g_hinit[((size_t)d * D_STATE + n) * NCHUNK + c];

    for (int t0 = tbase; t0 < tbase + CLEN; t0 += SC) {
        for (int idx = tid; idx < SC * 32; idx += 128) {
            int i = idx >> 5, cc = idx & 31;
            s_BC[i][cc] = g_xdbl[(size_t)(t0 + i) * XPROJ + 64 + cc];
        }
        for (int idx = tid; idx < SC * 8; idx += 128) {
            int i = idx >> 3, dd = idx & 7;
            size_t off = (size_t)(t0 + i) * D_INNER + d0 + dd;
            s_dt[i][dd] = g_dt[off];
            s_x [i][dd] = g_xconv[off];
        }
        __syncthreads();

        for (int i = 0; i < SC; i += 4) {
            float dAv[4], dbx[4], cv[4], xv[4], ya[4];
            #pragma unroll
            for (int j = 0; j < 4; j++) {
                float dtv = s_dt[i + j][ld];
                xv[j]  = s_x[i + j][ld];
                dAv[j] = __expf(dtv * Acoef);
                dbx[j] = dtv * xv[j] * s_BC[i + j][n];
                cv[j]  = s_BC[i + j][16 + n];
            }
            #pragma unroll
            for (int j = 0; j < 4; j++) {
                h = fmaf(dAv[j], h, dbx[j]);
                ya[j] = h * cv[j];
            }
            #pragma unroll
            for (int off = 8; off; off >>= 1) {
                #pragma unroll
                for (int j = 0; j < 4; j++)
                    ya[j] += __shfl_xor_sync(0xffffffffu, ya[j], off, 16);
            }
            if (n == 0) {
                #pragma unroll
                for (int j = 0; j < 4; j++)
                    s_y[i + j][ld] = fmaf(Dd, xv[j], ya[j]);
            }
        }
        __syncthreads();

        for (int idx = tid; idx < SC * 8; idx += 128) {
            int i = idx >> 3, dd = idx & 7;
            int t = t0 + i, dcol = d0 + dd;
            float z = g_xz[(size_t)t * 4096 + 2048 + dcol];
            float sz = z / (1.f + __expf(-z));
            float u = s_y[i][dd] * sz;
            __half uh, ul;
            split1(u, uh, ul);
            size_t o = (size_t)t * D_INNER + dcol;
            g_uh[o] = uh;
            g_ul[o] = ul;
        }
        __syncthreads();
    }
}

// ---------------- launch ----------------
extern "C" void kernel_launch(void* const* d_in, const int* in_sizes, int n_in,
                              void* d_out, int out_size)
{
    const float* x         = (const float*)d_in[0];
    const float* in_proj_w = (const float*)d_in[1];
    const float* conv_w    = (const float*)d_in[2];
    const float* conv_b    = (const float*)d_in[3];
    const float* x_proj_w  = (const float*)d_in[4];
    const float* dt_proj_w = (const float*)d_in[5];
    const float* dt_proj_b = (const float*)d_in[6];
    const float* A_log     = (const float*)d_in[7];
    const float* D_param   = (const float*)d_in[8];
    const float* out_proj_w= (const float*)d_in[9];
    float* out = (float*)d_out;

    float *xz, *dt;
    cudaGetSymbolAddress((void**)&xz, g_xz);
    cudaGetSymbolAddress((void**)&dt, g_dt);

    __half *xh, *xl, *wih, *xdh, *xdl, *dwh, *uh, *ul, *owh;
    cudaGetSymbolAddress((void**)&xh,  g_xh);  cudaGetSymbolAddress((void**)&xl,  g_xl);
    cudaGetSymbolAddress((void**)&wih, g_wih);
    cudaGetSymbolAddress((void**)&xdh, g_xdh); cudaGetSymbolAddress((void**)&xdl, g_xdl);
    cudaGetSymbolAddress((void**)&dwh, g_dwh);
    cudaGetSymbolAddress((void**)&uh,  g_uh);  cudaGetSymbolAddress((void**)&ul,  g_ul);
    cudaGetSymbolAddress((void**)&owh, g_owh);

    cudaFuncSetAttribute((const void*)mma_gemm<0, 2>, cudaFuncAttributeMaxDynamicSharedMemorySize, 2 * (2*128*80 + 10240));
    cudaFuncSetAttribute((const void*)mma_gemm<1, 2>, cudaFuncAttributeMaxDynamicSharedMemorySize, 2 * (2*128*80 + 10240));
    cudaFuncSetAttribute((const void*)mma_gemm<0, 1>, cudaFuncAttributeMaxDynamicSharedMemorySize, 2 * (2*64*80 + 10240));

    const int ST = 256;
    split_f16<<<(L_SEQ * D_MODEL + ST - 1) / ST, ST>>>(x, xh, xl, L_SEQ * D_MODEL);
    split_f16<<<(2 * D_INNER * D_MODEL + ST - 1) / ST, ST>>>(in_proj_w, wih, nullptr, 2 * D_INNER * D_MODEL);
    split_f16<<<(D_MODEL * D_INNER + ST - 1) / ST, ST>>>(out_proj_w, owh, nullptr, D_MODEL * D_INNER);

    // GEMM1: xz = x @ in_proj_w^T : (2048, 4096)
    {
        dim3 grid(4096 / 128, 2048 / 128);
        mma_gemm<0, 2><<<grid, 256, 2 * (2*128*80 + 10240)>>>(2048, 4096, 1024,
            xh, xl, 1024, wih, 1024, xz, 4096, nullptr);
    }
    // conv + SiLU
    conv_silu_kernel<<<(L_SEQ * D_INNER + ST - 1) / ST, ST>>>(conv_w, conv_b);
    // x_dbl (+ inline hi/lo split)
    xproj_kernel<<<L_SEQ / 32, 256>>>(x_proj_w);
    // dt weights split
    split_f16<<<(D_INNER * DT_RANK + ST - 1) / ST, ST>>>(dt_proj_w, dwh, nullptr, D_INNER * DT_RANK);
    // GEMM2: dt = softplus(x_dbl[:, :64] @ dt_proj_w^T + b)
    {
        dim3 grid(2048 / 128, 2048 / 128);
        mma_gemm<1, 2><<<grid, 256, 2 * (2*128*80 + 10240)>>>(2048, 2048, 64,
            xdh, xdl, XPROJ, dwh, DT_RANK, dt, 2048, dt_proj_b);
    }
    // parallel scan: partials -> combine -> final
    {
        dim3 g1(D_INNER / 8, NCHUNK);
        scan_part1<<<g1, 128>>>(A_log);
        scan_combine<<<(D_INNER * D_STATE + 255) / 256, 256>>>();
        scan_part3<<<g1, 128>>>(A_log, D_param);
    }
    // GEMM3: out = u @ out_proj_w^T  (BM=64 variant -> 256 CTAs)
    {
        dim3 grid(1024 / 128, 2048 / 64);
        mma_gemm<0, 1><<<grid, 256, 2 * (2*64*80 + 10240)>>>(2048, 1024, 2048,
            uh, ul, 2048, owh, 2048, out, 1024, nullptr);
    }
}

// round 8
// speedup vs baseline: 2.7114x; 1.1761x over previous
#include <cuda_runtime.h>
#include <cuda_fp16.h>
#include <cstdint>

// ---------------- problem constants ----------------
#define L_SEQ   2048
#define D_MODEL 1024
#define D_INNER 2048
#define D_STATE 16
#define DT_RANK 64
#define XPROJ   96
#define D_CONV  4
#define NCHUNK  16
#define CLEN    128     // L_SEQ / NCHUNK

// ---------------- fp32 scratch ----------------
__device__ float g_xz   [L_SEQ * 2 * D_INNER];
__device__ float g_xconv[L_SEQ * D_INNER];
__device__ float g_xdbl [L_SEQ * XPROJ];
__device__ float g_dt   [L_SEQ * D_INNER];
__device__ float g_hend [D_INNER * D_STATE * NCHUNK];
__device__ float g_decay[D_INNER * D_STATE * NCHUNK];
__device__ float g_hinit[D_INNER * D_STATE * NCHUNK];
__device__ float g_c3a  [L_SEQ * D_MODEL];   // split-K partials for GEMM3
__device__ float g_c3b  [L_SEQ * D_MODEL];

// ---------------- fp16 scratch ----------------
__device__ __half g_xh [L_SEQ * D_MODEL];
__device__ __half g_wih[2*D_INNER * D_MODEL];
__device__ __half g_xdh[L_SEQ * XPROJ],        g_xdl[L_SEQ * XPROJ];
__device__ __half g_dwh[D_INNER * DT_RANK];
__device__ __half g_uh [L_SEQ * D_INNER];
__device__ __half g_owh[D_MODEL * D_INNER];

// ================= helpers =================
__device__ __forceinline__ uint32_t smem_u32(const void* p) {
    uint32_t a;
    asm("{ .reg .u64 t; cvta.to.shared.u64 t, %1; cvt.u32.u64 %0, t; }" : "=r"(a) : "l"(p));
    return a;
}
__device__ __forceinline__ void cp16(uint32_t dst, const void* src) {
    asm volatile("cp.async.cg.shared.global [%0], [%1], 16;" :: "r"(dst), "l"(src));
}
__device__ __forceinline__ void cp_commit() {
    asm volatile("cp.async.commit_group;" ::: "memory");
}
__device__ __forceinline__ void cp_wait0() {
    asm volatile("cp.async.wait_group 0;" ::: "memory");
}
__device__ __forceinline__ void ldmat4(uint32_t* r, uint32_t addr) {
    asm volatile("ldmatrix.sync.aligned.m8n8.x4.shared.b16 {%0,%1,%2,%3}, [%4];"
                 : "=r"(r[0]), "=r"(r[1]), "=r"(r[2]), "=r"(r[3]) : "r"(addr));
}
__device__ __forceinline__ void mma_f16(float* d, const uint32_t* a, const uint32_t* b) {
    asm volatile("mma.sync.aligned.m16n8k16.row.col.f32.f16.f16.f32 "
                 "{%0,%1,%2,%3}, {%4,%5,%6,%7}, {%8,%9}, {%0,%1,%2,%3};"
                 : "+f"(d[0]), "+f"(d[1]), "+f"(d[2]), "+f"(d[3])
                 : "r"(a[0]), "r"(a[1]), "r"(a[2]), "r"(a[3]), "r"(b[0]), "r"(b[1]));
}
__device__ __forceinline__ void split1(float v, __half& h, __half& l) {
    h = __float2half_rn(v);
    l = __float2half_rn(v - __half2float(h));
}

// ================= fp32 -> fp16 convert (hi; optional lo) =================
__global__ void split_f16(const float* __restrict__ in,
                          __half* __restrict__ hi,
                          __half* __restrict__ lo, int n)
{
    int i = blockIdx.x * blockDim.x + threadIdx.x;
    if (i >= n) return;
    float v = in[i];
    __half h, l;
    split1(v, h, l);
    hi[i] = h;
    if (lo) lo[i] = l;
}

// ================= fp16 HMMA GEMM (BM = 64*MI, PASSES = A-split passes) =================
// Layout per stage: [Ah (PASSES==2: +Al)] [Bh], rows padded to 80B.
template <int MI, int PASSES>
__device__ __forceinline__ void load_stage(
    uint32_t st, const __half* Ah, const __half* Al, int lda,
    const __half* Bh, int ldb, int m0, int n0, int k0, int tid)
{
    constexpr int TA = 64 * MI * 80;
    #pragma unroll
    for (int j = 0; j < 2; j++) {
        int cl = tid * 2 + j;
        int r  = cl >> 2;
        int cc = cl & 3;
        uint32_t so = (uint32_t)(r * 80 + cc * 16);
        size_t goB = (size_t)(n0 + r) * ldb + k0 + cc * 8;
        if (MI == 2 || r < 64) {
            size_t goA = (size_t)(m0 + r) * lda + k0 + cc * 8;
            cp16(st + so, Ah + goA);
            if (PASSES == 2) cp16(st + TA + so, Al + goA);
        }
        cp16(st + PASSES * TA + so, Bh + goB);
    }
    cp_commit();
}

template <int EPI, int MI, int PASSES>
__global__ __launch_bounds__(256, 2)
void mma_gemm(int M, int N, int K,
              const __half* __restrict__ Ah, const __half* __restrict__ Al, int lda,
              const __half* __restrict__ Bh, int ldb,
              float* __restrict__ C, float* __restrict__ C2, int ldc,
              const float* __restrict__ bias)
{
    constexpr int BM    = 64 * MI;
    constexpr int TA    = BM * 80;
    constexpr int STAGE = PASSES * TA + 10240;

    extern __shared__ char smem[];
    uint32_t sbase = smem_u32(smem);

    int tid = threadIdx.x;
    int lane = tid & 31, wid = tid >> 5;
    int warp_m = wid & 3, warp_n = wid >> 2;
    int m0 = blockIdx.y * BM, n0 = blockIdx.x * 128;
    int kbase = blockIdx.z * K;               // split-K offset
    float* Cout = (blockIdx.z == 0) ? C : C2;

    float acc[MI][8][4];
    #pragma unroll
    for (int i = 0; i < MI; i++)
        #pragma unroll
        for (int j = 0; j < 8; j++)
            #pragma unroll
            for (int q = 0; q < 4; q++) acc[i][j][q] = 0.f;

    uint32_t a_off = (uint32_t)((warp_m * 16 * MI + (lane & 15)) * 80 + (lane >> 4) * 16);
    uint32_t b_off = (uint32_t)((warp_n * 64 + ((lane & 7) | ((lane & 16) >> 1))) * 80
                                + ((lane >> 3) & 1) * 16);

    int NK = K >> 5;
    load_stage<MI, PASSES>(sbase, Ah, Al, lda, Bh, ldb, m0, n0, kbase, tid);

    for (int kc = 0; kc < NK; kc++) {
        cp_wait0();
        __syncthreads();
        if (kc + 1 < NK)
            load_stage<MI, PASSES>(sbase + ((kc + 1) & 1) * STAGE,
                                   Ah, Al, lda, Bh, ldb, m0, n0, kbase + (kc + 1) * 32, tid);

        uint32_t st = sbase + (kc & 1) * STAGE;
        #pragma unroll
        for (int ks = 0; ks < 2; ks++) {
            uint32_t ah[MI][4], al[MI][4];
            #pragma unroll
            for (int mi = 0; mi < MI; mi++) {
                ldmat4(ah[mi], st + a_off + mi * 1280 + ks * 32);
                if (PASSES == 2) ldmat4(al[mi], st + TA + a_off + mi * 1280 + ks * 32);
            }
            #pragma unroll
            for (int half = 0; half < 2; half++) {
                uint32_t b[4][2];
                #pragma unroll
                for (int nj = 0; nj < 2; nj++) {
                    uint32_t r4[4];
                    ldmat4(r4, st + PASSES * TA + b_off + (half * 2 + nj) * 1280 + ks * 32);
                    b[2*nj][0] = r4[0]; b[2*nj][1] = r4[1];
                    b[2*nj+1][0] = r4[2]; b[2*nj+1][1] = r4[3];
                }
                #pragma unroll
                for (int mi = 0; mi < MI; mi++)
                    #pragma unroll
                    for (int ni = 0; ni < 4; ni++)
                        mma_f16(acc[mi][half * 4 + ni], ah[mi], b[ni]);
                if (PASSES == 2) {
                    #pragma unroll
                    for (int mi = 0; mi < MI; mi++)
                        #pragma unroll
                        for (int ni = 0; ni < 4; ni++)
                            mma_f16(acc[mi][half * 4 + ni], al[mi], b[ni]);
                }
            }
        }
        __syncthreads();
    }

    int gr = lane >> 2, gc = (lane & 3) * 2;
    int row_base = m0 + warp_m * 16 * MI;
    int col_base = n0 + warp_n * 64;
    #pragma unroll
    for (int mi = 0; mi < MI; mi++) {
        #pragma unroll
        for (int ni = 0; ni < 8; ni++) {
            int r0 = row_base + mi * 16 + gr;
            int c  = col_base + ni * 8 + gc;
            float v0 = acc[mi][ni][0], v1 = acc[mi][ni][1];
            float v2 = acc[mi][ni][2], v3 = acc[mi][ni][3];
            if (EPI == 1) {
                float b0 = bias[c], b1 = bias[c + 1];
                v0 += b0; v1 += b1; v2 += b0; v3 += b1;
                v0 = (v0 > 20.f) ? v0 : log1pf(__expf(v0));
                v1 = (v1 > 20.f) ? v1 : log1pf(__expf(v1));
                v2 = (v2 > 20.f) ? v2 : log1pf(__expf(v2));
                v3 = (v3 > 20.f) ? v3 : log1pf(__expf(v3));
            }
            *(float2*)(Cout + (size_t)r0 * ldc + c)       = make_float2(v0, v1);
            *(float2*)(Cout + (size_t)(r0 + 8) * ldc + c) = make_float2(v2, v3);
        }
    }
}

// ---------------- elementwise add (split-K reduce) ----------------
__global__ void add_f32(const float* __restrict__ a, const float* __restrict__ b,
                        float* __restrict__ o, int n4)
{
    int i = blockIdx.x * blockDim.x + threadIdx.x;
    if (i >= n4) return;
    float4 va = ((const float4*)a)[i];
    float4 vb = ((const float4*)b)[i];
    va.x += vb.x; va.y += vb.y; va.z += vb.z; va.w += vb.w;
    ((float4*)o)[i] = va;
}

// ---------------- depthwise causal conv (k=4) + bias + SiLU ----------------
__global__ void conv_silu_kernel(const float* __restrict__ conv_w,
                                 const float* __restrict__ conv_b)
{
    int idx = blockIdx.x * blockDim.x + threadIdx.x;
    if (idx >= L_SEQ * D_INNER) return;
    int t = idx / D_INNER;
    int d = idx % D_INNER;

    float w0 = conv_w[d * 4 + 0], w1 = conv_w[d * 4 + 1];
    float w2 = conv_w[d * 4 + 2], w3 = conv_w[d * 4 + 3];

    float v = conv_b[d];
    const float* xc = g_xz + d;
    if (t >= 3) v = fmaf(w0, xc[(size_t)(t - 3) * 4096], v);
    if (t >= 2) v = fmaf(w1, xc[(size_t)(t - 2) * 4096], v);
    if (t >= 1) v = fmaf(w2, xc[(size_t)(t - 1) * 4096], v);
    v = fmaf(w3, xc[(size_t)t * 4096], v);

    float s = 1.f / (1.f + __expf(-v));
    g_xconv[idx] = v * s;
}

// ---------------- x_dbl = x_conv @ x_proj_w^T (N=96), emits fp32 + hi/lo ----------------
__global__ __launch_bounds__(256, 2)
void xproj_kernel(const float* __restrict__ x_proj_w)
{
    __shared__ float sX[32][65];
    __shared__ float sW[96][64];

    int tid = threadIdx.x;
    int t0 = blockIdx.x * 32;
    int tl = tid & 31;
    int jg = tid >> 5;

    float acc[12];
    #pragma unroll
    for (int i = 0; i < 12; i++) acc[i] = 0.f;

    for (int k0 = 0; k0 < D_INNER; k0 += 64) {
        for (int idx = tid; idx < 32 * 64; idx += 256) {
            int r = idx >> 6, c = idx & 63;
            sX[r][c] = g_xconv[(size_t)(t0 + r) * D_INNER + k0 + c];
        }
        for (int idx = tid; idx < 96 * 64; idx += 256) {
            int r = idx >> 6, c = idx & 63;
            sW[r][c] = x_proj_w[(size_t)r * D_INNER + k0 + c];
        }
        __syncthreads();

        #pragma unroll 8
        for (int k = 0; k < 64; k++) {
            float xv = sX[tl][k];
            #pragma unroll
            for (int i = 0; i < 12; i++)
                acc[i] = fmaf(xv, sW[jg + 8 * i][k], acc[i]);
        }
        __syncthreads();
    }

    #pragma unroll
    for (int i = 0; i < 12; i++) {
        size_t o = (size_t)(t0 + tl) * XPROJ + jg + 8 * i;
        float v = acc[i];
        g_xdbl[o] = v;
        __half h, l;
        split1(v, h, l);
        g_xdh[o] = h;
        g_xdl[o] = l;
    }
}

// ---------------- scan pass 1: per-chunk partials ----------------
__global__ __launch_bounds__(128, 8)
void scan_part1(const float* __restrict__ A_log)
{
    const int SC = 64;
    __shared__ float s_B [SC][16];
    __shared__ float s_dt[SC][8];
    __shared__ float s_x [SC][8];

    int tid = threadIdx.x;
    int ld  = tid >> 4;
    int n   = tid & 15;
    int d0  = blockIdx.x * 8;
    int d   = d0 + ld;
    int c   = blockIdx.y;
    int tbase = c * CLEN;

    float Acoef = -__expf(A_log[(size_t)d * D_STATE + n]);
    float h = 0.f, sdt = 0.f;

    for (int t0 = tbase; t0 < tbase + CLEN; t0 += SC) {
        for (int idx = tid; idx < SC * 16; idx += 128) {
            int i = idx >> 4, cc = idx & 15;
            s_B[i][cc] = g_xdbl[(size_t)(t0 + i) * XPROJ + 64 + cc];
        }
        for (int idx = tid; idx < SC * 8; idx += 128) {
            int i = idx >> 3, dd = idx & 7;
            size_t off = (size_t)(t0 + i) * D_INNER + d0 + dd;
            s_dt[i][dd] = g_dt[off];
            s_x [i][dd] = g_xconv[off];
        }
        __syncthreads();

        for (int i = 0; i < SC; i += 4) {
            float dAv[4], dbx[4];
            #pragma unroll
            for (int j = 0; j < 4; j++) {
                float dtv = s_dt[i + j][ld];
                float xv  = s_x [i + j][ld];
                sdt += dtv;
                dAv[j] = __expf(dtv * Acoef);
                dbx[j] = dtv * xv * s_B[i + j][n];
            }
            #pragma unroll
            for (int j = 0; j < 4; j++)
                h = fmaf(dAv[j], h, dbx[j]);
        }
        __syncthreads();
    }

    size_t o = ((size_t)d * D_STATE + n) * NCHUNK + c;
    g_hend [o] = h;
    g_decay[o] = __expf(Acoef * sdt);
}

// ---------------- scan pass 2: combine ----------------
__global__ void scan_combine()
{
    int idx = blockIdx.x * blockDim.x + threadIdx.x;
    if (idx >= D_INNER * D_STATE) return;
    const float4* dec4 = (const float4*)(g_decay + (size_t)idx * NCHUNK);
    const float4* he4  = (const float4*)(g_hend  + (size_t)idx * NCHUNK);
    float4* hi4        = (float4*)(g_hinit + (size_t)idx * NCHUNK);
    float h = 0.f;
    #pragma unroll
    for (int q = 0; q < NCHUNK / 4; q++) {
        float4 dc = dec4[q], he = he4[q], out;
        out.x = h; h = fmaf(dc.x, h, he.x);
        out.y = h; h = fmaf(dc.y, h, he.y);
        out.z = h; h = fmaf(dc.z, h, he.z);
        out.w = h; h = fmaf(dc.w, h, he.w);
        hi4[q] = out;
    }
}

// ---------------- scan pass 3: full scan per chunk with y + u ----------------
__global__ __launch_bounds__(128, 8)
void scan_part3(const float* __restrict__ A_log,
                const float* __restrict__ D_param)
{
    const int SC = 64;
    __shared__ float s_BC[SC][32];
    __shared__ float s_dt[SC][8];
    __shared__ float s_x [SC][8];
    __shared__ float s_y [SC][8];

    int tid = threadIdx.x;
    int ld  = tid >> 4;
    int n   = tid & 15;
    int d0  = blockIdx.x * 8;
    int d   = d0 + ld;
    int c   = blockIdx.y;
    int tbase = c * CLEN;

    float Acoef = -__expf(A_log[(size_t)d * D_STATE + n]);
    float Dd    = D_param[d];
    float h = g_hinit[((size_t)d * D_STATE + n) * NCHUNK + c];

    for (int t0 = tbase; t0 < tbase + CLEN; t0 += SC) {
        for (int idx = tid; idx < SC * 32; idx += 128) {
            int i = idx >> 5, cc = idx & 31;
            s_BC[i][cc] = g_xdbl[(size_t)(t0 + i) * XPROJ + 64 + cc];
        }
        for (int idx = tid; idx < SC * 8; idx += 128) {
            int i = idx >> 3, dd = idx & 7;
            size_t off = (size_t)(t0 + i) * D_INNER + d0 + dd;
            s_dt[i][dd] = g_dt[off];
            s_x [i][dd] = g_xconv[off];
        }
        __syncthreads();

        for (int i = 0; i < SC; i += 4) {
            float dAv[4], dbx[4], cv[4], xv[4], ya[4];
            #pragma unroll
            for (int j = 0; j < 4; j++) {
                float dtv = s_dt[i + j][ld];
                xv[j]  = s_x[i + j][ld];
                dAv[j] = __expf(dtv * Acoef);
                dbx[j] = dtv * xv[j] * s_BC[i + j][n];
                cv[j]  = s_BC[i + j][16 + n];
            }
            #pragma unroll
            for (int j = 0; j < 4; j++) {
                h = fmaf(dAv[j], h, dbx[j]);
                ya[j] = h * cv[j];
            }
            #pragma unroll
            for (int off = 8; off; off >>= 1) {
                #pragma unroll
                for (int j = 0; j < 4; j++)
                    ya[j] += __shfl_xor_sync(0xffffffffu, ya[j], off, 16);
            }
            if (n == 0) {
                #pragma unroll
                for (int j = 0; j < 4; j++)
                    s_y[i + j][ld] = fmaf(Dd, xv[j], ya[j]);
            }
        }
        __syncthreads();

        for (int idx = tid; idx < SC * 8; idx += 128) {
            int i = idx >> 3, dd = idx & 7;
            int t = t0 + i, dcol = d0 + dd;
            float z = g_xz[(size_t)t * 4096 + 2048 + dcol];
            float sz = z / (1.f + __expf(-z));
            float u = s_y[i][dd] * sz;
            g_uh[(size_t)t * D_INNER + dcol] = __float2half_rn(u);
        }
        __syncthreads();
    }
}

// ---------------- launch ----------------
extern "C" void kernel_launch(void* const* d_in, const int* in_sizes, int n_in,
                              void* d_out, int out_size)
{
    const float* x         = (const float*)d_in[0];
    const float* in_proj_w = (const float*)d_in[1];
    const float* conv_w    = (const float*)d_in[2];
    const float* conv_b    = (const float*)d_in[3];
    const float* x_proj_w  = (const float*)d_in[4];
    const float* dt_proj_w = (const float*)d_in[5];
    const float* dt_proj_b = (const float*)d_in[6];
    const float* A_log     = (const float*)d_in[7];
    const float* D_param   = (const float*)d_in[8];
    const float* out_proj_w= (const float*)d_in[9];
    float* out = (float*)d_out;

    float *xz, *dt, *c3a, *c3b;
    cudaGetSymbolAddress((void**)&xz,  g_xz);
    cudaGetSymbolAddress((void**)&dt,  g_dt);
    cudaGetSymbolAddress((void**)&c3a, g_c3a);
    cudaGetSymbolAddress((void**)&c3b, g_c3b);

    __half *xh, *wih, *xdh, *xdl, *dwh, *uh, *owh;
    cudaGetSymbolAddress((void**)&xh,  g_xh);
    cudaGetSymbolAddress((void**)&wih, g_wih);
    cudaGetSymbolAddress((void**)&xdh, g_xdh); cudaGetSymbolAddress((void**)&xdl, g_xdl);
    cudaGetSymbolAddress((void**)&dwh, g_dwh);
    cudaGetSymbolAddress((void**)&uh,  g_uh);
    cudaGetSymbolAddress((void**)&owh, g_owh);

    const int SM1 = 2 * (1 * 10240 + 10240);   // MI=2, PASSES=1
    const int SM2 = 2 * (2 * 10240 + 10240);   // MI=2, PASSES=2
    cudaFuncSetAttribute((const void*)mma_gemm<0, 2, 1>, cudaFuncAttributeMaxDynamicSharedMemorySize, SM1);
    cudaFuncSetAttribute((const void*)mma_gemm<1, 2, 2>, cudaFuncAttributeMaxDynamicSharedMemorySize, SM2);

    const int ST = 256;
    split_f16<<<(L_SEQ * D_MODEL + ST - 1) / ST, ST>>>(x, xh, nullptr, L_SEQ * D_MODEL);
    split_f16<<<(2 * D_INNER * D_MODEL + ST - 1) / ST, ST>>>(in_proj_w, wih, nullptr, 2 * D_INNER * D_MODEL);
    split_f16<<<(D_MODEL * D_INNER + ST - 1) / ST, ST>>>(out_proj_w, owh, nullptr, D_MODEL * D_INNER);

    // GEMM1: xz = x @ in_proj_w^T : (2048, 4096), single-pass fp16
    {
        dim3 grid(4096 / 128, 2048 / 128, 1);
        mma_gemm<0, 2, 1><<<grid, 256, SM1>>>(2048, 4096, 1024,
            xh, nullptr, 1024, wih, 1024, xz, nullptr, 4096, nullptr);
    }
    // conv + SiLU
    conv_silu_kernel<<<(L_SEQ * D_INNER + ST - 1) / ST, ST>>>(conv_w, conv_b);
    // x_dbl (+ inline hi/lo split)
    xproj_kernel<<<L_SEQ / 32, 256>>>(x_proj_w);
    // dt weights
    split_f16<<<(D_INNER * DT_RANK + ST - 1) / ST, ST>>>(dt_proj_w, dwh, nullptr, D_INNER * DT_RANK);
    // GEMM2: dt = softplus(x_dbl[:, :64] @ dt_proj_w^T + b), 2-pass (accuracy-critical)
    {
        dim3 grid(2048 / 128, 2048 / 128, 1);
        mma_gemm<1, 2, 2><<<grid, 256, SM2>>>(2048, 2048, 64,
            xdh, xdl, XPROJ, dwh, DT_RANK, dt, nullptr, 2048, dt_proj_b);
    }
    // parallel scan
    {
        dim3 g1(D_INNER / 8, NCHUNK);
        scan_part1<<<g1, 128>>>(A_log);
        scan_combine<<<(D_INNER * D_STATE + 255) / 256, 256>>>();
        scan_part3<<<g1, 128>>>(A_log, D_param);
    }
    // GEMM3: out = u @ out_proj_w^T, single-pass fp16, split-K=2
    {
        dim3 grid(1024 / 128, 2048 / 128, 2);
        mma_gemm<0, 2, 1><<<grid, 256, SM1>>>(2048, 1024, 1024,
            uh, nullptr, 2048, owh, 2048, c3a, c3b, 1024, nullptr);
        add_f32<<<(L_SEQ * D_MODEL / 4 + ST - 1) / ST, ST>>>(c3a, c3b, out, L_SEQ * D_MODEL / 4);
    }
}